// round 1
// baseline (speedup 1.0000x reference)
#include <cuda_runtime.h>
#include <math.h>

#define NP  8192
#define DD  256
#define KNN 10

// ---------------- scratch (static device globals; no allocation) ------------
__device__ float g_f[NP * DD];     // projected features f = x @ Wd
__device__ float g_sq[NP];         // row squared norms of f
__device__ int   g_idx[NP * KNN];  // knn indices per row
__device__ float g_z[NP * DD];     // z = H^T @ (c*x)
__device__ float g_bcnt[NP];       // edge degrees (in-degree counts)
__device__ float g_h[NP * DD];     // h = x - 0.5*Mx

// ---------------- f32x2 helpers (sm_100a packed fp32) -----------------------
__device__ __forceinline__ unsigned long long pack2(float x, float y) {
    unsigned long long r;
    asm("mov.b64 %0, {%1, %2};" : "=l"(r) : "f"(x), "f"(y));
    return r;
}
__device__ __forceinline__ float2 unpack2(unsigned long long v) {
    float2 r;
    asm("mov.b64 {%0, %1}, %2;" : "=f"(r.x), "=f"(r.y) : "l"(v));
    return r;
}
#define FMA2(d, a, b) asm("fma.rn.f32x2 %0, %1, %2, %0;" : "+l"(d) : "l"(a), "l"(b))

// ---------------- generic 64x64 fp32 SGEMM body (M=8192, N=K=256) -----------
__device__ __forceinline__ void sgemm_body(const float* __restrict__ A,
                                           const float* __restrict__ B,
                                           const float* __restrict__ bias,
                                           float* __restrict__ C) {
    __shared__ float As[16][64];
    __shared__ float Bs[16][64];
    int t  = threadIdx.x;
    int tx = t % 16, ty = t / 16;
    int rb = blockIdx.y * 64, cb = blockIdx.x * 64;
    float acc[4][4] = {};
    for (int k0 = 0; k0 < DD; k0 += 16) {
        {   // A tile 64x16, stored transposed [k][row]
            int row = t >> 2, kq = (t & 3) * 4;
            float4 v = *(const float4*)&A[(rb + row) * DD + k0 + kq];
            As[kq + 0][row] = v.x; As[kq + 1][row] = v.y;
            As[kq + 2][row] = v.z; As[kq + 3][row] = v.w;
        }
        {   // B tile 16x64
            int krow = t >> 4, cq = (t & 15) * 4;
            *(float4*)&Bs[krow][cq] = *(const float4*)&B[(k0 + krow) * DD + cb + cq];
        }
        __syncthreads();
        #pragma unroll
        for (int kk = 0; kk < 16; kk++) {
            float4 av = *(const float4*)&As[kk][ty * 4];
            float4 bv = *(const float4*)&Bs[kk][tx * 4];
            float a[4] = {av.x, av.y, av.z, av.w};
            float b[4] = {bv.x, bv.y, bv.z, bv.w};
            #pragma unroll
            for (int i = 0; i < 4; i++)
                #pragma unroll
                for (int j = 0; j < 4; j++)
                    acc[i][j] = fmaf(a[i], b[j], acc[i][j]);
        }
        __syncthreads();
    }
    #pragma unroll
    for (int i = 0; i < 4; i++) {
        int r = rb + ty * 4 + i;
        #pragma unroll
        for (int j = 0; j < 4; j++) {
            int c = cb + tx * 4 + j;
            float v = acc[i][j];
            if (bias) v += bias[c];
            C[r * DD + c] = v;
        }
    }
}

__global__ __launch_bounds__(256) void gemm_f_kernel(const float* __restrict__ x,
                                                     const float* __restrict__ wd) {
    sgemm_body(x, wd, nullptr, g_f);
}
__global__ __launch_bounds__(256) void gemm_out_kernel(const float* __restrict__ w,
                                                       const float* __restrict__ bias,
                                                       float* __restrict__ out) {
    sgemm_body(g_h, w, bias, out);
}

// ---------------- row squared norms of f ------------------------------------
__global__ __launch_bounds__(256) void sqnorm_kernel() {
    int w = threadIdx.x >> 5, lane = threadIdx.x & 31;
    int row = blockIdx.x * 8 + w;
    const float* fr = &g_f[row * DD];
    float s = 0.f;
    #pragma unroll
    for (int q = 0; q < 8; q++) { float v = fr[lane + 32 * q]; s = fmaf(v, v, s); }
    #pragma unroll
    for (int o = 16; o > 0; o >>= 1) s += __shfl_xor_sync(0xffffffffu, s, o);
    if (lane == 0) g_sq[row] = s;
}

// ---------------- fused G = f@f^T + per-row top-10 --------------------------
// Block: 64 rows, loops column tiles of 128. key_j = sq[j] - 2*dot(f_i,f_j),
// monotone in dist. Maintains the 10 lexicographically smallest (key, j).
__global__ __launch_bounds__(256) void knn_kernel() {
    __shared__ float As[16][64];
    __shared__ float Bs[16][128];
    __shared__ float keys[64][65];   // 65 pad -> conflict-free row scans
    __shared__ float sqs[128];
    __shared__ float topv[64][KNN];
    __shared__ int   topi[64][KNN];
    __shared__ float worstv[64];

    int t  = threadIdx.x;
    int tx = t % 16, ty = t / 16;
    int rb = blockIdx.x * 64;
    const float INF = __int_as_float(0x7f800000);

    if (t < 64) {
        worstv[t] = INF;
        #pragma unroll
        for (int k = 0; k < KNN; k++) { topv[t][k] = INF; topi[t][k] = 0x7fffffff - k; }
    }
    __syncthreads();

    auto scan_half = [&](int jbase) {
        if (t < 64) {
            float wv = worstv[t];
            for (int c = 0; c < 64; c++) {
                float v = keys[t][c];
                if (v < wv) {     // strict: ties keep earlier index (jax semantics)
                    int pos = 0; float mv = topv[t][0]; int mi = topi[t][0];
                    #pragma unroll
                    for (int s2 = 1; s2 < KNN; s2++) {
                        float sv = topv[t][s2]; int si = topi[t][s2];
                        if (sv > mv || (sv == mv && si > mi)) { mv = sv; mi = si; pos = s2; }
                    }
                    topv[t][pos] = v; topi[t][pos] = jbase + c;
                    wv = topv[t][0];
                    #pragma unroll
                    for (int s2 = 1; s2 < KNN; s2++) wv = fmaxf(wv, topv[t][s2]);
                }
            }
            worstv[t] = wv;
        }
    };

    for (int jt = 0; jt < NP / 128; jt++) {
        int cb = jt * 128;
        if (t < 128) sqs[t] = g_sq[cb + t];

        unsigned long long acc[4][4];
        #pragma unroll
        for (int i = 0; i < 4; i++)
            #pragma unroll
            for (int cp = 0; cp < 4; cp++) acc[i][cp] = 0ULL;

        for (int k0 = 0; k0 < DD; k0 += 16) {
            __syncthreads();
            {   // A chunk 64x16 transposed
                int row = t >> 2, kq = (t & 3) * 4;
                float4 v = *(const float4*)&g_f[(rb + row) * DD + k0 + kq];
                As[kq + 0][row] = v.x; As[kq + 1][row] = v.y;
                As[kq + 2][row] = v.z; As[kq + 3][row] = v.w;
            }
            #pragma unroll
            for (int p = 0; p < 2; p++) {  // B chunk 128x16 transposed
                int u = p * 256 + t;
                int col = u >> 2, kq = (u & 3) * 4;
                float4 v = *(const float4*)&g_f[(cb + col) * DD + k0 + kq];
                Bs[kq + 0][col] = v.x; Bs[kq + 1][col] = v.y;
                Bs[kq + 2][col] = v.z; Bs[kq + 3][col] = v.w;
            }
            __syncthreads();
            #pragma unroll
            for (int kk = 0; kk < 16; kk++) {
                float4 av = *(const float4*)&As[kk][ty * 4];
                float4 b0 = *(const float4*)&Bs[kk][tx * 8];
                float4 b1 = *(const float4*)&Bs[kk][tx * 8 + 4];
                unsigned long long aa0 = pack2(av.x, av.x), aa1 = pack2(av.y, av.y);
                unsigned long long aa2 = pack2(av.z, av.z), aa3 = pack2(av.w, av.w);
                unsigned long long bb0 = pack2(b0.x, b0.y), bb1 = pack2(b0.z, b0.w);
                unsigned long long bb2 = pack2(b1.x, b1.y), bb3 = pack2(b1.z, b1.w);
                FMA2(acc[0][0], aa0, bb0); FMA2(acc[0][1], aa0, bb1);
                FMA2(acc[0][2], aa0, bb2); FMA2(acc[0][3], aa0, bb3);
                FMA2(acc[1][0], aa1, bb0); FMA2(acc[1][1], aa1, bb1);
                FMA2(acc[1][2], aa1, bb2); FMA2(acc[1][3], aa1, bb3);
                FMA2(acc[2][0], aa2, bb0); FMA2(acc[2][1], aa2, bb1);
                FMA2(acc[2][2], aa2, bb2); FMA2(acc[2][3], aa2, bb3);
                FMA2(acc[3][0], aa3, bb0); FMA2(acc[3][1], aa3, bb1);
                FMA2(acc[3][2], aa3, bb2); FMA2(acc[3][3], aa3, bb3);
            }
        }
        __syncthreads();

        // phase 0: columns 0..63 of this tile
        if (tx < 8) {
            #pragma unroll
            for (int i = 0; i < 4; i++) {
                int row = ty * 4 + i;
                #pragma unroll
                for (int cp = 0; cp < 4; cp++) {
                    float2 u = unpack2(acc[i][cp]);
                    int cl = tx * 8 + cp * 2;
                    keys[row][cl]     = sqs[cl]     - 2.f * u.x;
                    keys[row][cl + 1] = sqs[cl + 1] - 2.f * u.y;
                }
            }
        }
        __syncthreads();
        scan_half(cb);
        __syncthreads();
        // phase 1: columns 64..127
        if (tx >= 8) {
            #pragma unroll
            for (int i = 0; i < 4; i++) {
                int row = ty * 4 + i;
                #pragma unroll
                for (int cp = 0; cp < 4; cp++) {
                    float2 u = unpack2(acc[i][cp]);
                    int cl = tx * 8 + cp * 2;
                    keys[row][cl - 64] = sqs[cl]     - 2.f * u.x;
                    keys[row][cl - 63] = sqs[cl + 1] - 2.f * u.y;
                }
            }
        }
        __syncthreads();
        scan_half(cb + 64);
        // first __syncthreads of next jt's k0-loop protects keys/sqs reuse
    }
    __syncthreads();
    if (t < 64) {
        #pragma unroll
        for (int k = 0; k < KNN; k++) g_idx[(rb + t) * KNN + k] = topi[t][k];
    }
}

// ---------------- Laplacian apply -------------------------------------------
__global__ __launch_bounds__(256) void zero_kernel() {
    int tid = blockIdx.x * blockDim.x + threadIdx.x;
    int stride = gridDim.x * blockDim.x;
    float4 z4 = make_float4(0.f, 0.f, 0.f, 0.f);
    for (int i = tid; i < NP * DD / 4; i += stride) ((float4*)g_z)[i] = z4;
    if (tid < NP) g_bcnt[tid] = 0.f;
}

// z[e] += c * x[i] for e in idx[i];  b_deg[e] += 1
__global__ __launch_bounds__(256) void scatter_kernel(const float* __restrict__ x) {
    __shared__ int sidx[4][KNN];
    int t = threadIdx.x;
    int i0 = blockIdx.x * 4;
    if (t < 4 * KNN) {
        int r = t / KNN, k = t % KNN;
        int e = g_idx[(i0 + r) * KNN + k];
        sidx[r][k] = e;
        atomicAdd(&g_bcnt[e], 1.0f);
    }
    __syncthreads();
    int s = t >> 6;
    int cq = (t & 63) << 2;
    const float cnorm = 0.31622776601683794f;  // 1/sqrt(10+1e-10)
    float4 xv = *(const float4*)&x[(i0 + s) * DD + cq];
    float4 y = make_float4(xv.x * cnorm, xv.y * cnorm, xv.z * cnorm, xv.w * cnorm);
    #pragma unroll
    for (int k = 0; k < KNN; k++) {
        int e = sidx[s][k];
        float* p = &g_z[e * DD + cq];
        asm volatile("red.global.add.v4.f32 [%0], {%1, %2, %3, %4};"
                     :: "l"(p), "f"(y.x), "f"(y.y), "f"(y.z), "f"(y.w) : "memory");
    }
}

// h[i] = x[i] - 0.5*c * sum_k b_is[e_k] * z[e_k]
__global__ __launch_bounds__(256) void gather_kernel(const float* __restrict__ x) {
    __shared__ int   sidx[4][KNN];
    __shared__ float sbis[4][KNN];
    int t = threadIdx.x;
    int i0 = blockIdx.x * 4;
    if (t < 4 * KNN) {
        int r = t / KNN, k = t % KNN;
        int e = g_idx[(i0 + r) * KNN + k];
        sidx[r][k] = e;
        sbis[r][k] = 1.0f / sqrtf(g_bcnt[e] + 1e-10f);
    }
    __syncthreads();
    int s = t >> 6;
    int cq = (t & 63) << 2;
    float4 acc = make_float4(0.f, 0.f, 0.f, 0.f);
    #pragma unroll
    for (int k = 0; k < KNN; k++) {
        int e = sidx[s][k];
        float b = sbis[s][k];
        float4 zv = *(const float4*)&g_z[e * DD + cq];
        acc.x = fmaf(b, zv.x, acc.x);
        acc.y = fmaf(b, zv.y, acc.y);
        acc.z = fmaf(b, zv.z, acc.z);
        acc.w = fmaf(b, zv.w, acc.w);
    }
    const float hc = 0.5f * 0.31622776601683794f;
    float4 xv = *(const float4*)&x[(i0 + s) * DD + cq];
    float4 h;
    h.x = xv.x - hc * acc.x;
    h.y = xv.y - hc * acc.y;
    h.z = xv.z - hc * acc.z;
    h.w = xv.w - hc * acc.w;
    *(float4*)&g_h[(i0 + s) * DD + cq] = h;
}

// ---------------- launch -----------------------------------------------------
extern "C" void kernel_launch(void* const* d_in, const int* in_sizes, int n_in,
                              void* d_out, int out_size) {
    const float* x    = (const float*)d_in[0];   // (8192, 256)
    const float* w    = (const float*)d_in[1];   // (256, 256)
    const float* wd   = (const float*)d_in[2];   // (256, 256)
    const float* bias = (const float*)d_in[3];   // (256,)
    float* out = (float*)d_out;                  // (8192, 256)

    gemm_f_kernel<<<dim3(DD / 64, NP / 64), 256>>>(x, wd);
    sqnorm_kernel<<<NP / 8, 256>>>();
    zero_kernel<<<1024, 256>>>();
    knn_kernel<<<NP / 64, 256>>>();
    scatter_kernel<<<NP / 4, 256>>>(x);
    gather_kernel<<<NP / 4, 256>>>(x);
    gemm_out_kernel<<<dim3(DD / 64, NP / 64), 256>>>(w, bias, out);
}

// round 2
// speedup vs baseline: 1.7346x; 1.7346x over previous
#include <cuda_runtime.h>
#include <math.h>

#define NP  8192
#define DD  256
#define KNN 10

// ---------------- scratch (static device globals; no allocation) ------------
__device__ float g_fT[DD * NP];       // f^T : fT[k][r] = f[r][k]
__device__ float g_sq[NP];            // row squared norms of f
__device__ int   g_idx[NP * KNN];     // knn indices per row
__device__ float g_pv[NP * 4 * KNN];  // per-band candidate values
__device__ int   g_pi[NP * 4 * KNN];  // per-band candidate indices
__device__ float g_z[NP * DD];        // z = H^T @ (c*x)
__device__ float g_bcnt[NP];          // edge degrees
__device__ float g_h[NP * DD];        // h = x - 0.5*Mx

// ---------------- f32x2 helpers (packed fp32, sm_100a) ----------------------
__device__ __forceinline__ unsigned long long pack2(float x, float y) {
    unsigned long long r;
    asm("mov.b64 %0, {%1, %2};" : "=l"(r) : "f"(x), "f"(y));
    return r;
}
__device__ __forceinline__ float2 unpack2(unsigned long long v) {
    float2 r;
    asm("mov.b64 {%0, %1}, %2;" : "=f"(r.x), "=f"(r.y) : "l"(v));
    return r;
}
#define FMA2(d, a, b) asm("fma.rn.f32x2 %0, %1, %2, %0;" : "+l"(d) : "l"(a), "l"(b))

// ---------------- GEMM 1: fT = (x @ Wd)^T -----------------------------------
__global__ __launch_bounds__(256) void gemm_f_kernel(const float* __restrict__ A,
                                                     const float* __restrict__ B) {
    __shared__ float As[16][64];
    __shared__ float Bs[16][64];
    int t  = threadIdx.x;
    int tx = t % 16, ty = t / 16;
    int rb = blockIdx.y * 64, cb = blockIdx.x * 64;
    float acc[4][4] = {};
    for (int k0 = 0; k0 < DD; k0 += 16) {
        {
            int row = t >> 2, kq = (t & 3) * 4;
            float4 v = *(const float4*)&A[(rb + row) * DD + k0 + kq];
            As[kq + 0][row] = v.x; As[kq + 1][row] = v.y;
            As[kq + 2][row] = v.z; As[kq + 3][row] = v.w;
        }
        {
            int krow = t >> 4, cq = (t & 15) * 4;
            *(float4*)&Bs[krow][cq] = *(const float4*)&B[(k0 + krow) * DD + cb + cq];
        }
        __syncthreads();
        #pragma unroll
        for (int kk = 0; kk < 16; kk++) {
            float4 av = *(const float4*)&As[kk][ty * 4];
            float4 bv = *(const float4*)&Bs[kk][tx * 4];
            float a[4] = {av.x, av.y, av.z, av.w};
            float b[4] = {bv.x, bv.y, bv.z, bv.w};
            #pragma unroll
            for (int i = 0; i < 4; i++)
                #pragma unroll
                for (int j = 0; j < 4; j++)
                    acc[i][j] = fmaf(a[i], b[j], acc[i][j]);
        }
        __syncthreads();
    }
    // transposed epilogue: fT[c][r], float4 along r
    #pragma unroll
    for (int j = 0; j < 4; j++) {
        int c = cb + tx * 4 + j;
        float4 vv = make_float4(acc[0][j], acc[1][j], acc[2][j], acc[3][j]);
        *(float4*)&g_fT[c * NP + rb + ty * 4] = vv;
    }
}

// ---------------- GEMM 2: out = h @ W + bias --------------------------------
__global__ __launch_bounds__(256) void gemm_out_kernel(const float* __restrict__ B,
                                                       const float* __restrict__ bias,
                                                       float* __restrict__ C) {
    __shared__ float As[16][64];
    __shared__ float Bs[16][64];
    int t  = threadIdx.x;
    int tx = t % 16, ty = t / 16;
    int rb = blockIdx.y * 64, cb = blockIdx.x * 64;
    const float* A = g_h;
    float acc[4][4] = {};
    for (int k0 = 0; k0 < DD; k0 += 16) {
        {
            int row = t >> 2, kq = (t & 3) * 4;
            float4 v = *(const float4*)&A[(rb + row) * DD + k0 + kq];
            As[kq + 0][row] = v.x; As[kq + 1][row] = v.y;
            As[kq + 2][row] = v.z; As[kq + 3][row] = v.w;
        }
        {
            int krow = t >> 4, cq = (t & 15) * 4;
            *(float4*)&Bs[krow][cq] = *(const float4*)&B[(k0 + krow) * DD + cb + cq];
        }
        __syncthreads();
        #pragma unroll
        for (int kk = 0; kk < 16; kk++) {
            float4 av = *(const float4*)&As[kk][ty * 4];
            float4 bv = *(const float4*)&Bs[kk][tx * 4];
            float a[4] = {av.x, av.y, av.z, av.w};
            float b[4] = {bv.x, bv.y, bv.z, bv.w};
            #pragma unroll
            for (int i = 0; i < 4; i++)
                #pragma unroll
                for (int j = 0; j < 4; j++)
                    acc[i][j] = fmaf(a[i], b[j], acc[i][j]);
        }
        __syncthreads();
    }
    #pragma unroll
    for (int i = 0; i < 4; i++) {
        int r = rb + ty * 4 + i;
        #pragma unroll
        for (int j = 0; j < 4; j++) {
            int c = cb + tx * 4 + j;
            C[r * DD + c] = acc[i][j] + bias[c];
        }
    }
}

// ---------------- row squared norms (from fT, coalesced) --------------------
__global__ __launch_bounds__(256) void sqnorm_kernel() {
    int r = blockIdx.x * 256 + threadIdx.x;
    float s0 = 0.f, s1 = 0.f, s2 = 0.f, s3 = 0.f;
    #pragma unroll 4
    for (int k = 0; k < DD; k += 4) {
        float v0 = g_fT[(k + 0) * NP + r];
        float v1 = g_fT[(k + 1) * NP + r];
        float v2 = g_fT[(k + 2) * NP + r];
        float v3 = g_fT[(k + 3) * NP + r];
        s0 = fmaf(v0, v0, s0); s1 = fmaf(v1, v1, s1);
        s2 = fmaf(v2, v2, s2); s3 = fmaf(v3, v3, s3);
    }
    g_sq[r] = (s0 + s1) + (s2 + s3);
}

// ---------------- fused G = f@f^T + per-(row,band) top-10 -------------------
// Block: 64 rows x 256-col tiles. 8x8 register tile per thread (f32x2 pairs).
// Each thread additionally scans one (row, 16-col band) per 64-col chunk,
// keeping a private register top-10; 4 bands/row merged by merge_kernel.
__global__ __launch_bounds__(256, 1) void knn_kernel() {
    __shared__ float As[16][64];
    __shared__ float Bs[16][256];
    __shared__ float keys[64][65];
    __shared__ float sqs[256];

    int t  = threadIdx.x;
    int tx = t & 31;   // col group (8 cols)
    int ty = t >> 5;   // row group (8 rows)
    int rb = blockIdx.x * 64;

    const float INF = __int_as_float(0x7f800000);
    float topv[KNN]; int topi[KNN];
    #pragma unroll
    for (int k = 0; k < KNN; k++) { topv[k] = INF; topi[k] = 0x7ffffff0 + k; }
    float wv = INF;

    int srow  = t & 63;   // scanner row
    int sband = t >> 6;   // scanner band (16 cols within 64-chunk)

    int lk = t >> 4;         // k-row this thread loads
    int lo = (t & 15) * 4;   // float4 offset

    unsigned long long acc[8][4];

    for (int jt = 0; jt < NP / 256; jt++) {
        int cb = jt * 256;
        sqs[t] = g_sq[cb + t];

        #pragma unroll
        for (int i = 0; i < 8; i++)
            #pragma unroll
            for (int c = 0; c < 4; c++) acc[i][c] = 0ULL;

        // prefetch chunk 0
        float4 pa, pb0, pb1, pb2, pb3;
        pa  = *(const float4*)&g_fT[lk * NP + rb + lo];
        pb0 = *(const float4*)&g_fT[lk * NP + cb + lo];
        pb1 = *(const float4*)&g_fT[lk * NP + cb + 64 + lo];
        pb2 = *(const float4*)&g_fT[lk * NP + cb + 128 + lo];
        pb3 = *(const float4*)&g_fT[lk * NP + cb + 192 + lo];

        for (int kc = 0; kc < 16; kc++) {
            __syncthreads();
            *(float4*)&As[lk][lo]        = pa;
            *(float4*)&Bs[lk][lo]        = pb0;
            *(float4*)&Bs[lk][lo + 64]   = pb1;
            *(float4*)&Bs[lk][lo + 128]  = pb2;
            *(float4*)&Bs[lk][lo + 192]  = pb3;
            __syncthreads();
            if (kc < 15) {   // prefetch next chunk (overlaps FMA block below)
                int k0 = (kc + 1) * 16 + lk;
                pa  = *(const float4*)&g_fT[k0 * NP + rb + lo];
                pb0 = *(const float4*)&g_fT[k0 * NP + cb + lo];
                pb1 = *(const float4*)&g_fT[k0 * NP + cb + 64 + lo];
                pb2 = *(const float4*)&g_fT[k0 * NP + cb + 128 + lo];
                pb3 = *(const float4*)&g_fT[k0 * NP + cb + 192 + lo];
            }
            #pragma unroll
            for (int kk = 0; kk < 16; kk++) {
                float4 a0 = *(const float4*)&As[kk][ty * 8];      // warp broadcast
                float4 a1 = *(const float4*)&As[kk][ty * 8 + 4];
                float4 b0 = *(const float4*)&Bs[kk][tx * 8];
                float4 b1 = *(const float4*)&Bs[kk][tx * 8 + 4];
                unsigned long long bb0 = pack2(b0.x, b0.y), bb1 = pack2(b0.z, b0.w);
                unsigned long long bb2 = pack2(b1.x, b1.y), bb3 = pack2(b1.z, b1.w);
                float ar[8] = {a0.x, a0.y, a0.z, a0.w, a1.x, a1.y, a1.z, a1.w};
                #pragma unroll
                for (int r = 0; r < 8; r++) {
                    unsigned long long aa = pack2(ar[r], ar[r]);
                    FMA2(acc[r][0], aa, bb0);
                    FMA2(acc[r][1], aa, bb1);
                    FMA2(acc[r][2], aa, bb2);
                    FMA2(acc[r][3], aa, bb3);
                }
            }
        }

        // keys + scan over four 64-col chunks
        #pragma unroll 1
        for (int ch = 0; ch < 4; ch++) {
            __syncthreads();
            if ((tx >> 3) == ch) {
                int cl0 = (tx & 7) * 8;
                #pragma unroll
                for (int r = 0; r < 8; r++) {
                    int row = ty * 8 + r;
                    #pragma unroll
                    for (int cp = 0; cp < 4; cp++) {
                        float2 u = unpack2(acc[r][cp]);
                        int cg = tx * 8 + cp * 2;
                        keys[row][cl0 + cp * 2]     = sqs[cg]     - 2.f * u.x;
                        keys[row][cl0 + cp * 2 + 1] = sqs[cg + 1] - 2.f * u.y;
                    }
                }
            }
            __syncthreads();
            int jbase = cb + ch * 64 + sband * 16;
            #pragma unroll 1
            for (int c = 0; c < 16; c++) {
                float v = keys[srow][sband * 16 + c];
                if (v < wv) {   // strict: ties keep earlier index
                    int pos = 0; float mv = topv[0]; int mi = topi[0];
                    #pragma unroll
                    for (int s = 1; s < KNN; s++)
                        if (topv[s] > mv || (topv[s] == mv && topi[s] > mi)) {
                            mv = topv[s]; mi = topi[s]; pos = s;
                        }
                    #pragma unroll
                    for (int s = 0; s < KNN; s++)
                        if (s == pos) { topv[s] = v; topi[s] = jbase + c; }
                    wv = topv[0];
                    #pragma unroll
                    for (int s = 1; s < KNN; s++) wv = fmaxf(wv, topv[s]);
                }
            }
        }
    }

    // emit per-band candidates
    int row = rb + srow;
    #pragma unroll
    for (int k = 0; k < KNN; k++) {
        g_pv[(row * 4 + sband) * KNN + k] = topv[k];
        g_pi[(row * 4 + sband) * KNN + k] = topi[k];
    }
}

// ---------------- merge 4 bands -> final top-10 per row ---------------------
__global__ __launch_bounds__(256) void merge_kernel() {
    int row = blockIdx.x * 256 + threadIdx.x;
    float v[4 * KNN]; int id[4 * KNN];
    #pragma unroll
    for (int s = 0; s < 4 * KNN; s++) {
        v[s]  = g_pv[row * 4 * KNN + s];
        id[s] = g_pi[row * 4 * KNN + s];
    }
    const float INF = __int_as_float(0x7f800000);
    #pragma unroll
    for (int k = 0; k < KNN; k++) {
        int bp = 0; float bv = v[0]; int bi = id[0];
        #pragma unroll
        for (int s = 1; s < 4 * KNN; s++)
            if (v[s] < bv || (v[s] == bv && id[s] < bi)) { bv = v[s]; bi = id[s]; bp = s; }
        g_idx[row * KNN + k] = bi;
        v[bp] = INF; id[bp] = 0x7fffffff;
    }
}

// ---------------- Laplacian apply -------------------------------------------
__global__ __launch_bounds__(256) void zero_kernel() {
    int tid = blockIdx.x * blockDim.x + threadIdx.x;
    int stride = gridDim.x * blockDim.x;
    float4 z4 = make_float4(0.f, 0.f, 0.f, 0.f);
    for (int i = tid; i < NP * DD / 4; i += stride) ((float4*)g_z)[i] = z4;
    if (tid < NP) g_bcnt[tid] = 0.f;
}

__global__ __launch_bounds__(256) void scatter_kernel(const float* __restrict__ x) {
    __shared__ int sidx[4][KNN];
    int t = threadIdx.x;
    int i0 = blockIdx.x * 4;
    if (t < 4 * KNN) {
        int r = t / KNN, k = t % KNN;
        int e = g_idx[(i0 + r) * KNN + k];
        sidx[r][k] = e;
        atomicAdd(&g_bcnt[e], 1.0f);
    }
    __syncthreads();
    int s = t >> 6;
    int cq = (t & 63) << 2;
    const float cnorm = 0.31622776601683794f;  // 1/sqrt(10+1e-10)
    float4 xv = *(const float4*)&x[(i0 + s) * DD + cq];
    float4 y = make_float4(xv.x * cnorm, xv.y * cnorm, xv.z * cnorm, xv.w * cnorm);
    #pragma unroll
    for (int k = 0; k < KNN; k++) {
        int e = sidx[s][k];
        float* p = &g_z[e * DD + cq];
        asm volatile("red.global.add.v4.f32 [%0], {%1, %2, %3, %4};"
                     :: "l"(p), "f"(y.x), "f"(y.y), "f"(y.z), "f"(y.w) : "memory");
    }
}

__global__ __launch_bounds__(256) void gather_kernel(const float* __restrict__ x) {
    __shared__ int   sidx[4][KNN];
    __shared__ float sbis[4][KNN];
    int t = threadIdx.x;
    int i0 = blockIdx.x * 4;
    if (t < 4 * KNN) {
        int r = t / KNN, k = t % KNN;
        int e = g_idx[(i0 + r) * KNN + k];
        sidx[r][k] = e;
        sbis[r][k] = 1.0f / sqrtf(g_bcnt[e] + 1e-10f);
    }
    __syncthreads();
    int s = t >> 6;
    int cq = (t & 63) << 2;
    float4 acc = make_float4(0.f, 0.f, 0.f, 0.f);
    #pragma unroll
    for (int k = 0; k < KNN; k++) {
        int e = sidx[s][k];
        float b = sbis[s][k];
        float4 zv = *(const float4*)&g_z[e * DD + cq];
        acc.x = fmaf(b, zv.x, acc.x);
        acc.y = fmaf(b, zv.y, acc.y);
        acc.z = fmaf(b, zv.z, acc.z);
        acc.w = fmaf(b, zv.w, acc.w);
    }
    const float hc = 0.5f * 0.31622776601683794f;
    float4 xv = *(const float4*)&x[(i0 + s) * DD + cq];
    float4 h;
    h.x = xv.x - hc * acc.x;
    h.y = xv.y - hc * acc.y;
    h.z = xv.z - hc * acc.z;
    h.w = xv.w - hc * acc.w;
    *(float4*)&g_h[(i0 + s) * DD + cq] = h;
}

// ---------------- launch -----------------------------------------------------
extern "C" void kernel_launch(void* const* d_in, const int* in_sizes, int n_in,
                              void* d_out, int out_size) {
    const float* x    = (const float*)d_in[0];   // (8192, 256)
    const float* w    = (const float*)d_in[1];   // (256, 256)
    const float* wd   = (const float*)d_in[2];   // (256, 256)
    const float* bias = (const float*)d_in[3];   // (256,)
    float* out = (float*)d_out;                  // (8192, 256)

    gemm_f_kernel<<<dim3(DD / 64, NP / 64), 256>>>(x, wd);
    sqnorm_kernel<<<NP / 256, 256>>>();
    zero_kernel<<<1024, 256>>>();
    knn_kernel<<<NP / 64, 256>>>();
    merge_kernel<<<NP / 256, 256>>>();
    scatter_kernel<<<NP / 4, 256>>>(x);
    gather_kernel<<<NP / 4, 256>>>(x);
    gemm_out_kernel<<<dim3(DD / 64, NP / 64), 256>>>(w, bias, out);
}

// round 5
// speedup vs baseline: 3.2579x; 1.8782x over previous
#include <cuda_runtime.h>
#include <cuda_bf16.h>
#include <cstdint>
#include <math.h>

#define NP  8192
#define DD  256
#define KNN 10
#define NC  16        // candidates kept per (row, band)
#define KST 129       // keys smem row stride (floats) — conflict-free scan

// ---------------- scratch (static device globals; no allocation) ------------
__device__ float         g_f[NP * DD];    // f fp32 row-major
__device__ __nv_bfloat16 g_fb[NP * DD];   // f bf16 row-major
__device__ float         g_sq[NP];
__device__ int           g_pi[NP * 64];   // 64 candidates per row
__device__ int           g_idx[NP * KNN];
__device__ float         g_z[NP * DD];
__device__ float         g_bcnt[NP];
__device__ float         g_h[NP * DD];

// ---------------- ptx helpers ------------------------------------------------
__device__ __forceinline__ uint32_t smem_u32(const void* p) {
    uint32_t a;
    asm("{ .reg .u64 t; cvta.to.shared.u64 t, %1; cvt.u32.u64 %0, t; }" : "=r"(a) : "l"(p));
    return a;
}
__device__ __forceinline__ void cpasync16(uint32_t dst, const void* src) {
    asm volatile("cp.async.cg.shared.global [%0], [%1], 16;" :: "r"(dst), "l"(src));
}
#define CP_COMMIT() asm volatile("cp.async.commit_group;" ::: "memory")
#define CP_WAIT0()  asm volatile("cp.async.wait_group 0;" ::: "memory")

__device__ __forceinline__ void ldsm_x4(uint32_t* r, uint32_t addr) {
    asm volatile("ldmatrix.sync.aligned.m8n8.x4.shared.b16 {%0,%1,%2,%3}, [%4];"
                 : "=r"(r[0]), "=r"(r[1]), "=r"(r[2]), "=r"(r[3]) : "r"(addr));
}
__device__ __forceinline__ void mma_bf16(float* c, const uint32_t* a,
                                         uint32_t b0, uint32_t b1) {
    asm volatile("mma.sync.aligned.m16n8k16.row.col.f32.bf16.bf16.f32 "
                 "{%0,%1,%2,%3}, {%4,%5,%6,%7}, {%8,%9}, {%0,%1,%2,%3};"
                 : "+f"(c[0]), "+f"(c[1]), "+f"(c[2]), "+f"(c[3])
                 : "r"(a[0]), "r"(a[1]), "r"(a[2]), "r"(a[3]), "r"(b0), "r"(b1));
}

// ---------------- GEMM 1: g_f = x @ Wd (fp32) + g_fb (bf16) -----------------
__global__ __launch_bounds__(256) void gemm_f_kernel(const float* __restrict__ A,
                                                     const float* __restrict__ B) {
    __shared__ float As[16][64];
    __shared__ float Bs[16][64];
    int t  = threadIdx.x;
    int tx = t % 16, ty = t / 16;
    int rb = blockIdx.y * 64, cb = blockIdx.x * 64;
    float acc[4][4] = {};
    for (int k0 = 0; k0 < DD; k0 += 16) {
        {
            int row = t >> 2, kq = (t & 3) * 4;
            float4 v = *(const float4*)&A[(rb + row) * DD + k0 + kq];
            As[kq + 0][row] = v.x; As[kq + 1][row] = v.y;
            As[kq + 2][row] = v.z; As[kq + 3][row] = v.w;
        }
        {
            int krow = t >> 4, cq = (t & 15) * 4;
            *(float4*)&Bs[krow][cq] = *(const float4*)&B[(k0 + krow) * DD + cb + cq];
        }
        __syncthreads();
        #pragma unroll
        for (int kk = 0; kk < 16; kk++) {
            float4 av = *(const float4*)&As[kk][ty * 4];
            float4 bv = *(const float4*)&Bs[kk][tx * 4];
            float a[4] = {av.x, av.y, av.z, av.w};
            float b[4] = {bv.x, bv.y, bv.z, bv.w};
            #pragma unroll
            for (int i = 0; i < 4; i++)
                #pragma unroll
                for (int j = 0; j < 4; j++)
                    acc[i][j] = fmaf(a[i], b[j], acc[i][j]);
        }
        __syncthreads();
    }
    #pragma unroll
    for (int i = 0; i < 4; i++) {
        int r = rb + ty * 4 + i;
        int c = cb + tx * 4;
        float4 vv = make_float4(acc[i][0], acc[i][1], acc[i][2], acc[i][3]);
        *(float4*)&g_f[r * DD + c] = vv;
        __nv_bfloat162 b01 = __floats2bfloat162_rn(vv.x, vv.y);
        __nv_bfloat162 b23 = __floats2bfloat162_rn(vv.z, vv.w);
        uint2 pk;
        pk.x = *(uint32_t*)&b01;
        pk.y = *(uint32_t*)&b23;
        *(uint2*)&g_fb[r * DD + c] = pk;
    }
}

// ---------------- GEMM 2: out = h @ W + bias --------------------------------
__global__ __launch_bounds__(256) void gemm_out_kernel(const float* __restrict__ B,
                                                       const float* __restrict__ bias,
                                                       float* __restrict__ C) {
    __shared__ float As[16][64];
    __shared__ float Bs[16][64];
    int t  = threadIdx.x;
    int tx = t % 16, ty = t / 16;
    int rb = blockIdx.y * 64, cb = blockIdx.x * 64;
    const float* A = g_h;
    float acc[4][4] = {};
    for (int k0 = 0; k0 < DD; k0 += 16) {
        {
            int row = t >> 2, kq = (t & 3) * 4;
            float4 v = *(const float4*)&A[(rb + row) * DD + k0 + kq];
            As[kq + 0][row] = v.x; As[kq + 1][row] = v.y;
            As[kq + 2][row] = v.z; As[kq + 3][row] = v.w;
        }
        {
            int krow = t >> 4, cq = (t & 15) * 4;
            *(float4*)&Bs[krow][cq] = *(const float4*)&B[(k0 + krow) * DD + cb + cq];
        }
        __syncthreads();
        #pragma unroll
        for (int kk = 0; kk < 16; kk++) {
            float4 av = *(const float4*)&As[kk][ty * 4];
            float4 bv = *(const float4*)&Bs[kk][tx * 4];
            float a[4] = {av.x, av.y, av.z, av.w};
            float b[4] = {bv.x, bv.y, bv.z, bv.w};
            #pragma unroll
            for (int i = 0; i < 4; i++)
                #pragma unroll
                for (int j = 0; j < 4; j++)
                    acc[i][j] = fmaf(a[i], b[j], acc[i][j]);
        }
        __syncthreads();
    }
    #pragma unroll
    for (int i = 0; i < 4; i++) {
        int r = rb + ty * 4 + i;
        #pragma unroll
        for (int j = 0; j < 4; j++) {
            int c = cb + tx * 4 + j;
            C[r * DD + c] = acc[i][j] + bias[c];
        }
    }
}

// ---------------- row squared norms of f ------------------------------------
__global__ __launch_bounds__(256) void sqnorm_kernel() {
    int w = threadIdx.x >> 5, lane = threadIdx.x & 31;
    int row = blockIdx.x * 8 + w;
    const float* fr = &g_f[row * DD];
    float s = 0.f;
    #pragma unroll
    for (int q = 0; q < 8; q++) { float v = fr[lane + 32 * q]; s = fmaf(v, v, s); }
    #pragma unroll
    for (int o = 16; o > 0; o >>= 1) s += __shfl_xor_sync(0xffffffffu, s, o);
    if (lane == 0) g_sq[row] = s;
}

// ---------------- coarse knn: mma.sync bf16 ---------------------------------
// CTA: 128 rows x one 4096-col half. A tile 128x256 bf16 resident (64KB);
// B streamed as 128x128 k-chunks, double-buffered cp.async. 8 warps as 4x2:
// warp tile 32 rows x 64 cols via m16n8k16. Keys -> smem (stride 129),
// 256 scanner threads keep register top-16 per (row, 64-col band).
__global__ __launch_bounds__(256, 1) void knn_coarse_kernel() {
    extern __shared__ char dsm[];
    float* keys = (float*)(dsm + 131072);             // [128][129]
    int t = threadIdx.x, lane = t & 31, warp = t >> 5;
    int wm = warp & 3, wn = warp >> 2;
    int rb = blockIdx.y * 128;
    int half = blockIdx.x;
    int cbase = half * (NP / 2);

    uint32_t Abase = smem_u32(dsm);
    uint32_t Bbase0 = Abase + 65536;
    uint32_t Bbase1 = Abase + 98304;

    // A tile (128 rows x 256 k), granule-swizzled: g' = g ^ (row&7)
    #pragma unroll
    for (int i = 0; i < 16; i++) {
        int idx = t + 256 * i;
        int id = idx >> 5, g = idx & 31;
        cpasync16(Abase + id * 512 + ((g ^ (id & 7)) << 4),
                  &g_fb[(rb + id) * DD + g * 8]);
    }
    // B chunk 0 (j=0, kc=0): 128 ids x 128 k
    #pragma unroll
    for (int i = 0; i < 8; i++) {
        int idx = t + 256 * i;
        int id = idx >> 4, g = idx & 15;
        cpasync16(Bbase0 + id * 256 + ((g ^ (id & 7)) << 4),
                  &g_fb[(cbase + id) * DD + g * 8]);
    }
    CP_COMMIT();

    // per-thread ldmatrix addressing
    int arow = wm * 32 + (lane & 7) + ((lane & 8) ? 8 : 0);
    uint32_t Arow0 = Abase + arow * 512;
    uint32_t Arow1 = Arow0 + 16 * 512;
    int sw  = lane & 7;                 // (row&7) for both A and B patterns
    int aka = (lane & 16) ? 1 : 0;      // A: k +8 selector
    int bro = (lane & 7) + ((lane & 16) ? 8 : 0);   // B: n-row within pair
    int bka = (lane & 8) ? 1 : 0;       // B: k +8 selector

    const float INF = __int_as_float(0x7f800000);
    float tv[NC]; int ti[NC];
    #pragma unroll
    for (int s = 0; s < NC; s++) { tv[s] = INF; ti[s] = 0; }
    float wv = INF;
    int srow = t & 127, sband = t >> 7;

    float acc[2][8][4];

    for (int cc = 0; cc < 64; cc++) {
        int jt = cc >> 1, kc = cc & 1;
        CP_WAIT0();
        __syncthreads();

        // prefetch next B chunk into the other buffer (overlaps MMA below)
        if (cc + 1 < 64) {
            int jn = (cc + 1) >> 1, kn = (cc + 1) & 1;
            uint32_t bb = ((cc + 1) & 1) ? Bbase1 : Bbase0;
            const __nv_bfloat16* src = &g_fb[(cbase + jn * 128) * DD + kn * 128];
            #pragma unroll
            for (int i = 0; i < 8; i++) {
                int idx = t + 256 * i;
                int id = idx >> 4, g = idx & 15;
                cpasync16(bb + id * 256 + ((g ^ (id & 7)) << 4), src + id * DD + g * 8);
            }
            CP_COMMIT();
        }

        if (kc == 0) {
            #pragma unroll
            for (int mi = 0; mi < 2; mi++)
                #pragma unroll
                for (int ni = 0; ni < 8; ni++)
                    #pragma unroll
                    for (int q = 0; q < 4; q++) acc[mi][ni][q] = 0.f;
        }

        uint32_t Bb = (cc & 1) ? Bbase1 : Bbase0;
        #pragma unroll
        for (int s = 0; s < 8; s++) {
            int ga = kc * 16 + s * 2 + aka;
            uint32_t a0[4], a1[4];
            ldsm_x4(a0, Arow0 + ((ga ^ sw) << 4));
            ldsm_x4(a1, Arow1 + ((ga ^ sw) << 4));
            int gb = s * 2 + bka;
            #pragma unroll
            for (int pi = 0; pi < 4; pi++) {
                int nrow = wn * 64 + pi * 16 + bro;
                uint32_t b[4];
                ldsm_x4(b, Bb + nrow * 256 + ((gb ^ sw) << 4));
                mma_bf16(acc[0][pi * 2 + 0], a0, b[0], b[1]);
                mma_bf16(acc[0][pi * 2 + 1], a0, b[2], b[3]);
                mma_bf16(acc[1][pi * 2 + 0], a1, b[0], b[1]);
                mma_bf16(acc[1][pi * 2 + 1], a1, b[2], b[3]);
            }
        }

        if (kc == 1) {
            // write keys (scan of previous tile ended with a barrier)
            int cbg = cbase + jt * 128;
            int rq = lane >> 2, cq = (lane & 3) * 2;
            #pragma unroll
            for (int ni = 0; ni < 8; ni++) {
                int col = wn * 64 + ni * 8 + cq;
                float sq0 = g_sq[cbg + col], sq1 = g_sq[cbg + col + 1];
                #pragma unroll
                for (int mi = 0; mi < 2; mi++) {
                    int r0 = wm * 32 + mi * 16 + rq;
                    float* a4 = acc[mi][ni];
                    keys[r0 * KST + col]           = sq0 - 2.f * a4[0];
                    keys[r0 * KST + col + 1]       = sq1 - 2.f * a4[1];
                    keys[(r0 + 8) * KST + col]     = sq0 - 2.f * a4[2];
                    keys[(r0 + 8) * KST + col + 1] = sq1 - 2.f * a4[3];
                }
            }
            __syncthreads();
            // scan: thread (srow, sband) over 64 cols
            int jb = cbg + sband * 64;
            const float* kr = &keys[srow * KST + sband * 64];
            #pragma unroll 4
            for (int c = 0; c < 64; c++) {
                float v = kr[c];
                if (v < wv) {
                    int pos = 0; float mv = tv[0];
                    #pragma unroll
                    for (int s = 1; s < NC; s++)
                        if (tv[s] > mv) { mv = tv[s]; pos = s; }
                    #pragma unroll
                    for (int s = 0; s < NC; s++)
                        if (s == pos) { tv[s] = v; ti[s] = jb + c; }
                    wv = tv[0];
                    #pragma unroll
                    for (int s = 1; s < NC; s++) wv = fmaxf(wv, tv[s]);
                }
            }
            __syncthreads();
        }
    }

    int row = rb + srow;
    #pragma unroll
    for (int s = 0; s < NC; s++)
        g_pi[row * 64 + half * 32 + sband * 16 + s] = ti[s];
}

// ---------------- exact refine: 64 candidates -> top-10 ---------------------
__global__ __launch_bounds__(256) void refine_kernel() {
    __shared__ float fi[8][DD];
    int t = threadIdx.x, w = t >> 5, l = t & 31;
    int i = blockIdx.x * 8 + w;
    #pragma unroll
    for (int q = 0; q < 8; q++) fi[w][l + 32 * q] = g_f[i * DD + l + 32 * q];
    __syncwarp();
    int j0 = g_pi[i * 64 + l];
    int j1 = g_pi[i * 64 + 32 + l];
    const float4* f0 = (const float4*)&g_f[j0 * DD];
    const float4* f1 = (const float4*)&g_f[j1 * DD];
    float p0 = 0.f, p1 = 0.f, p2 = 0.f, p3 = 0.f;
    float q0 = 0.f, q1 = 0.f, q2 = 0.f, q3 = 0.f;
    #pragma unroll 8
    for (int k = 0; k < DD / 4; k++) {
        float4 v0 = f0[k], v1 = f1[k];
        float x0 = fi[w][4 * k], x1 = fi[w][4 * k + 1];
        float x2 = fi[w][4 * k + 2], x3 = fi[w][4 * k + 3];
        p0 = fmaf(x0, v0.x, p0); p1 = fmaf(x1, v0.y, p1);
        p2 = fmaf(x2, v0.z, p2); p3 = fmaf(x3, v0.w, p3);
        q0 = fmaf(x0, v1.x, q0); q1 = fmaf(x1, v1.y, q1);
        q2 = fmaf(x2, v1.z, q2); q3 = fmaf(x3, v1.w, q3);
    }
    float key0 = g_sq[j0] - 2.f * ((p0 + p1) + (p2 + p3));
    float key1 = g_sq[j1] - 2.f * ((q0 + q1) + (q2 + q3));
    unsigned kb0 = __float_as_uint(key0);
    kb0 = (kb0 & 0x80000000u) ? ~kb0 : (kb0 | 0x80000000u);
    unsigned kb1 = __float_as_uint(key1);
    kb1 = (kb1 & 0x80000000u) ? ~kb1 : (kb1 | 0x80000000u);
    unsigned long long pk0 = ((unsigned long long)kb0 << 32) | (unsigned)j0;
    unsigned long long pk1 = ((unsigned long long)kb1 << 32) | (unsigned)j1;
    #pragma unroll
    for (int r = 0; r < KNN; r++) {
        unsigned long long m = pk0 < pk1 ? pk0 : pk1;
        #pragma unroll
        for (int o = 16; o > 0; o >>= 1) {
            unsigned long long other = __shfl_xor_sync(0xffffffffu, m, o);
            if (other < m) m = other;
        }
        if (l == 0) g_idx[i * KNN + r] = (int)(m & 0xffffffffULL);
        if (pk0 == m) pk0 = 0xFFFFFFFFFFFFFFFFULL;
        else if (pk1 == m) pk1 = 0xFFFFFFFFFFFFFFFFULL;
    }
}

// ---------------- Laplacian apply -------------------------------------------
__global__ __launch_bounds__(256) void zero_kernel() {
    int tid = blockIdx.x * blockDim.x + threadIdx.x;
    int stride = gridDim.x * blockDim.x;
    float4 z4 = make_float4(0.f, 0.f, 0.f, 0.f);
    for (int i = tid; i < NP * DD / 4; i += stride) ((float4*)g_z)[i] = z4;
    if (tid < NP) g_bcnt[tid] = 0.f;
}

__global__ __launch_bounds__(256) void scatter_kernel(const float* __restrict__ x) {
    __shared__ int sidx[4][KNN];
    int t = threadIdx.x;
    int i0 = blockIdx.x * 4;
    if (t < 4 * KNN) {
        int r = t / KNN, k = t % KNN;
        int e = g_idx[(i0 + r) * KNN + k];
        sidx[r][k] = e;
        atomicAdd(&g_bcnt[e], 1.0f);
    }
    __syncthreads();
    int s = t >> 6;
    int cq = (t & 63) << 2;
    const float cnorm = 0.31622776601683794f;  // 1/sqrt(10+1e-10)
    float4 xv = *(const float4*)&x[(i0 + s) * DD + cq];
    float4 y = make_float4(xv.x * cnorm, xv.y * cnorm, xv.z * cnorm, xv.w * cnorm);
    #pragma unroll
    for (int k = 0; k < KNN; k++) {
        int e = sidx[s][k];
        float* p = &g_z[e * DD + cq];
        asm volatile("red.global.add.v4.f32 [%0], {%1, %2, %3, %4};"
                     :: "l"(p), "f"(y.x), "f"(y.y), "f"(y.z), "f"(y.w) : "memory");
    }
}

__global__ __launch_bounds__(256) void gather_kernel(const float* __restrict__ x) {
    __shared__ int   sidx[4][KNN];
    __shared__ float sbis[4][KNN];
    int t = threadIdx.x;
    int i0 = blockIdx.x * 4;
    if (t < 4 * KNN) {
        int r = t / KNN, k = t % KNN;
        int e = g_idx[(i0 + r) * KNN + k];
        sidx[r][k] = e;
        sbis[r][k] = 1.0f / sqrtf(g_bcnt[e] + 1e-10f);
    }
    __syncthreads();
    int s = t >> 6;
    int cq = (t & 63) << 2;
    float4 acc = make_float4(0.f, 0.f, 0.f, 0.f);
    #pragma unroll
    for (int k = 0; k < KNN; k++) {
        int e = sidx[s][k];
        float b = sbis[s][k];
        float4 zv = *(const float4*)&g_z[e * DD + cq];
        acc.x = fmaf(b, zv.x, acc.x);
        acc.y = fmaf(b, zv.y, acc.y);
        acc.z = fmaf(b, zv.z, acc.z);
        acc.w = fmaf(b, zv.w, acc.w);
    }
    const float hc = 0.5f * 0.31622776601683794f;
    float4 xv = *(const float4*)&x[(i0 + s) * DD + cq];
    float4 h;
    h.x = xv.x - hc * acc.x;
    h.y = xv.y - hc * acc.y;
    h.z = xv.z - hc * acc.z;
    h.w = xv.w - hc * acc.w;
    *(float4*)&g_h[(i0 + s) * DD + cq] = h;
}

// ---------------- launch -----------------------------------------------------
extern "C" void kernel_launch(void* const* d_in, const int* in_sizes, int n_in,
                              void* d_out, int out_size) {
    const float* x    = (const float*)d_in[0];   // (8192, 256)
    const float* w    = (const float*)d_in[1];   // (256, 256)
    const float* wd   = (const float*)d_in[2];   // (256, 256)
    const float* bias = (const float*)d_in[3];   // (256,)
    float* out = (float*)d_out;                  // (8192, 256)

    const int KNN_SMEM = 131072 + 128 * KST * 4;   // A + 2xB + keys = 197120
    cudaFuncSetAttribute(knn_coarse_kernel,
                         cudaFuncAttributeMaxDynamicSharedMemorySize, KNN_SMEM);

    gemm_f_kernel<<<dim3(DD / 64, NP / 64), 256>>>(x, wd);
    sqnorm_kernel<<<NP / 8, 256>>>();
    zero_kernel<<<1024, 256>>>();
    knn_coarse_kernel<<<dim3(2, NP / 128), 256, KNN_SMEM>>>();
    refine_kernel<<<NP / 8, 256>>>();
    scatter_kernel<<<NP / 4, 256>>>(x);
    gather_kernel<<<NP / 4, 256>>>(x);
    gemm_out_kernel<<<dim3(DD / 64, NP / 64), 256>>>(w, bias, out);
}

// round 6
// speedup vs baseline: 3.3249x; 1.0206x over previous
#include <cuda_runtime.h>
#include <cuda_bf16.h>
#include <cstdint>
#include <math.h>

#define NP  8192
#define DD  256
#define KNN 10
#define NC  16        // candidates kept per (row, band)
#define KST 129       // keys smem row stride (floats) — conflict-free scan

// ---------------- scratch (static device globals; no allocation) ------------
__device__ float         g_f[NP * DD];    // f fp32 row-major
__device__ __nv_bfloat16 g_fb[NP * DD];   // f bf16 row-major
__device__ float         g_sq[NP];
__device__ int           g_pi[NP * 64];   // 64 candidates per row
__device__ int           g_idx[NP * KNN];
__device__ float         g_z[NP * DD];
__device__ float         g_bcnt[NP];
__device__ float         g_h[NP * DD];

// ---------------- ptx helpers ------------------------------------------------
__device__ __forceinline__ uint32_t smem_u32(const void* p) {
    uint32_t a;
    asm("{ .reg .u64 t; cvta.to.shared.u64 t, %1; cvt.u32.u64 %0, t; }" : "=r"(a) : "l"(p));
    return a;
}
__device__ __forceinline__ void cpasync16(uint32_t dst, const void* src) {
    asm volatile("cp.async.cg.shared.global [%0], [%1], 16;" :: "r"(dst), "l"(src));
}
#define CP_COMMIT() asm volatile("cp.async.commit_group;" ::: "memory")
#define CP_WAIT0()  asm volatile("cp.async.wait_group 0;" ::: "memory")

__device__ __forceinline__ void ldsm_x4(uint32_t* r, uint32_t addr) {
    asm volatile("ldmatrix.sync.aligned.m8n8.x4.shared.b16 {%0,%1,%2,%3}, [%4];"
                 : "=r"(r[0]), "=r"(r[1]), "=r"(r[2]), "=r"(r[3]) : "r"(addr));
}
__device__ __forceinline__ void mma_bf16(float* c, const uint32_t* a,
                                         uint32_t b0, uint32_t b1) {
    asm volatile("mma.sync.aligned.m16n8k16.row.col.f32.bf16.bf16.f32 "
                 "{%0,%1,%2,%3}, {%4,%5,%6,%7}, {%8,%9}, {%0,%1,%2,%3};"
                 : "+f"(c[0]), "+f"(c[1]), "+f"(c[2]), "+f"(c[3])
                 : "r"(a[0]), "r"(a[1]), "r"(a[2]), "r"(a[3]), "r"(b0), "r"(b1));
}

// ---------------- GEMM 1: g_f = x @ Wd (fp32) + g_fb (bf16) -----------------
__global__ __launch_bounds__(256) void gemm_f_kernel(const float* __restrict__ A,
                                                     const float* __restrict__ B) {
    __shared__ float As[16][64];
    __shared__ float Bs[16][64];
    int t  = threadIdx.x;
    int tx = t % 16, ty = t / 16;
    int rb = blockIdx.y * 64, cb = blockIdx.x * 64;
    float acc[4][4] = {};
    for (int k0 = 0; k0 < DD; k0 += 16) {
        {
            int row = t >> 2, kq = (t & 3) * 4;
            float4 v = *(const float4*)&A[(rb + row) * DD + k0 + kq];
            As[kq + 0][row] = v.x; As[kq + 1][row] = v.y;
            As[kq + 2][row] = v.z; As[kq + 3][row] = v.w;
        }
        {
            int krow = t >> 4, cq = (t & 15) * 4;
            *(float4*)&Bs[krow][cq] = *(const float4*)&B[(k0 + krow) * DD + cb + cq];
        }
        __syncthreads();
        #pragma unroll
        for (int kk = 0; kk < 16; kk++) {
            float4 av = *(const float4*)&As[kk][ty * 4];
            float4 bv = *(const float4*)&Bs[kk][tx * 4];
            float a[4] = {av.x, av.y, av.z, av.w};
            float b[4] = {bv.x, bv.y, bv.z, bv.w};
            #pragma unroll
            for (int i = 0; i < 4; i++)
                #pragma unroll
                for (int j = 0; j < 4; j++)
                    acc[i][j] = fmaf(a[i], b[j], acc[i][j]);
        }
        __syncthreads();
    }
    #pragma unroll
    for (int i = 0; i < 4; i++) {
        int r = rb + ty * 4 + i;
        int c = cb + tx * 4;
        float4 vv = make_float4(acc[i][0], acc[i][1], acc[i][2], acc[i][3]);
        *(float4*)&g_f[r * DD + c] = vv;
        __nv_bfloat162 b01 = __floats2bfloat162_rn(vv.x, vv.y);
        __nv_bfloat162 b23 = __floats2bfloat162_rn(vv.z, vv.w);
        uint2 pk;
        pk.x = *(uint32_t*)&b01;
        pk.y = *(uint32_t*)&b23;
        *(uint2*)&g_fb[r * DD + c] = pk;
    }
}

// ---------------- GEMM 2: out = h @ W + bias --------------------------------
__global__ __launch_bounds__(256) void gemm_out_kernel(const float* __restrict__ B,
                                                       const float* __restrict__ bias,
                                                       float* __restrict__ C) {
    __shared__ float As[16][64];
    __shared__ float Bs[16][64];
    int t  = threadIdx.x;
    int tx = t % 16, ty = t / 16;
    int rb = blockIdx.y * 64, cb = blockIdx.x * 64;
    const float* A = g_h;
    float acc[4][4] = {};
    for (int k0 = 0; k0 < DD; k0 += 16) {
        {
            int row = t >> 2, kq = (t & 3) * 4;
            float4 v = *(const float4*)&A[(rb + row) * DD + k0 + kq];
            As[kq + 0][row] = v.x; As[kq + 1][row] = v.y;
            As[kq + 2][row] = v.z; As[kq + 3][row] = v.w;
        }
        {
            int krow = t >> 4, cq = (t & 15) * 4;
            *(float4*)&Bs[krow][cq] = *(const float4*)&B[(k0 + krow) * DD + cb + cq];
        }
        __syncthreads();
        #pragma unroll
        for (int kk = 0; kk < 16; kk++) {
            float4 av = *(const float4*)&As[kk][ty * 4];
            float4 bv = *(const float4*)&Bs[kk][tx * 4];
            float a[4] = {av.x, av.y, av.z, av.w};
            float b[4] = {bv.x, bv.y, bv.z, bv.w};
            #pragma unroll
            for (int i = 0; i < 4; i++)
                #pragma unroll
                for (int j = 0; j < 4; j++)
                    acc[i][j] = fmaf(a[i], b[j], acc[i][j]);
        }
        __syncthreads();
    }
    #pragma unroll
    for (int i = 0; i < 4; i++) {
        int r = rb + ty * 4 + i;
        #pragma unroll
        for (int j = 0; j < 4; j++) {
            int c = cb + tx * 4 + j;
            C[r * DD + c] = acc[i][j] + bias[c];
        }
    }
}

// ---------------- row squared norms of f ------------------------------------
__global__ __launch_bounds__(256) void sqnorm_kernel() {
    int w = threadIdx.x >> 5, lane = threadIdx.x & 31;
    int row = blockIdx.x * 8 + w;
    const float* fr = &g_f[row * DD];
    float s = 0.f;
    #pragma unroll
    for (int q = 0; q < 8; q++) { float v = fr[lane + 32 * q]; s = fmaf(v, v, s); }
    #pragma unroll
    for (int o = 16; o > 0; o >>= 1) s += __shfl_xor_sync(0xffffffffu, s, o);
    if (lane == 0) g_sq[row] = s;
}

// ---------------- coarse knn: mma.sync bf16, 2 CTAs/SM ----------------------
// CTA: 64 rows x one 4096-col half. A tile 64x256 bf16 resident (32KB);
// B streamed as 128-id x 64-k chunks (16KB), double-buffered cp.async.
// 8 warps as 2x4: warp tile 32 rows x 32 cols via m16n8k16. Keys -> smem
// (stride 129); 128 scanner threads keep register top-16 per (row, 64-col band).
// smem total ~99KB -> 2 CTAs/SM so scan of one CTA overlaps MMA of the other.
__global__ __launch_bounds__(256, 2) void knn_coarse_kernel() {
    extern __shared__ char dsm[];
    float* keys = (float*)(dsm + 65536);              // [64][129]
    float* sqs  = (float*)(dsm + 65536 + 64 * KST * 4);  // [128]
    int t = threadIdx.x, lane = t & 31, warp = t >> 5;
    int wm = warp & 1, wn = warp >> 1;
    int rb = blockIdx.y * 64;
    int half = blockIdx.x;
    int cbase = half * (NP / 2);

    uint32_t Abase  = smem_u32(dsm);
    uint32_t Bbase0 = Abase + 32768;
    uint32_t Bbase1 = Abase + 49152;

    // A tile (64 rows x 256 k), granule-swizzled: g' = g ^ (row&7)
    #pragma unroll
    for (int i = 0; i < 8; i++) {
        int idx = t + 256 * i;
        int id = idx >> 5, g = idx & 31;
        cpasync16(Abase + id * 512 + ((g ^ (id & 7)) << 4),
                  &g_fb[(rb + id) * DD + g * 8]);
    }
    // B chunk 0: 128 ids x 64 k
    #pragma unroll
    for (int i = 0; i < 4; i++) {
        int idx = t + 256 * i;
        int id = idx >> 3, g = idx & 7;
        cpasync16(Bbase0 + id * 128 + ((g ^ (id & 7)) << 4),
                  &g_fb[(cbase + id) * DD + g * 8]);
    }
    CP_COMMIT();

    // per-thread ldmatrix addressing (same fragment mapping as R5)
    int arow = wm * 32 + (lane & 7) + ((lane & 8) ? 8 : 0);
    uint32_t Arow0 = Abase + arow * 512;
    uint32_t Arow1 = Arow0 + 16 * 512;
    int sw  = lane & 7;
    int aka = (lane & 16) ? 1 : 0;                   // A: k +8 selector
    int bro = (lane & 7) + ((lane & 16) ? 8 : 0);    // B: n-row within pair
    int bka = (lane & 8) ? 1 : 0;                    // B: k +8 selector

    const float INF = __int_as_float(0x7f800000);
    float tv[NC]; int ti[NC];
    #pragma unroll
    for (int s = 0; s < NC; s++) { tv[s] = INF; ti[s] = 0; }
    float wv = INF;
    int srow = t & 63, sband = (t >> 6) & 1;         // scanners: t < 128

    float acc[2][4][4];

    for (int cc = 0; cc < 128; cc++) {
        int jt = cc >> 2, kc = cc & 3;
        CP_WAIT0();
        __syncthreads();

        if (kc == 0 && t < 128) sqs[t] = g_sq[cbase + jt * 128 + t];

        // prefetch next chunk into the other buffer (overlaps MMA/scan below)
        if (cc + 1 < 128) {
            int jn = (cc + 1) >> 2, kn = (cc + 1) & 3;
            uint32_t bb = ((cc + 1) & 1) ? Bbase1 : Bbase0;
            const __nv_bfloat16* src = &g_fb[(cbase + jn * 128) * DD + kn * 64];
            #pragma unroll
            for (int i = 0; i < 4; i++) {
                int idx = t + 256 * i;
                int id = idx >> 3, g = idx & 7;
                cpasync16(bb + id * 128 + ((g ^ (id & 7)) << 4), src + id * DD + g * 8);
            }
            CP_COMMIT();
        }

        if (kc == 0) {
            #pragma unroll
            for (int mi = 0; mi < 2; mi++)
                #pragma unroll
                for (int ni = 0; ni < 4; ni++)
                    #pragma unroll
                    for (int q = 0; q < 4; q++) acc[mi][ni][q] = 0.f;
        }

        uint32_t Bb = (cc & 1) ? Bbase1 : Bbase0;
        #pragma unroll
        for (int s = 0; s < 4; s++) {                // 4 k16 steps per 64-k chunk
            int ga = kc * 8 + s * 2 + aka;           // A k-granule (global)
            uint32_t a0[4], a1[4];
            ldsm_x4(a0, Arow0 + ((ga ^ sw) << 4));
            ldsm_x4(a1, Arow1 + ((ga ^ sw) << 4));
            int gb = s * 2 + bka;                    // B k-granule (chunk-local)
            #pragma unroll
            for (int pi = 0; pi < 2; pi++) {         // two n16 groups -> 32 cols
                int nrow = wn * 32 + pi * 16 + bro;
                uint32_t b[4];
                ldsm_x4(b, Bb + nrow * 128 + ((gb ^ sw) << 4));
                mma_bf16(acc[0][pi * 2 + 0], a0, b[0], b[1]);
                mma_bf16(acc[0][pi * 2 + 1], a0, b[2], b[3]);
                mma_bf16(acc[1][pi * 2 + 0], a1, b[0], b[1]);
                mma_bf16(acc[1][pi * 2 + 1], a1, b[2], b[3]);
            }
        }

        if (kc == 3) {
            // write keys for this 128-col tile
            int rq = lane >> 2, cq = (lane & 3) * 2;
            #pragma unroll
            for (int ni = 0; ni < 4; ni++) {
                int col = wn * 32 + ni * 8 + cq;
                float sq0 = sqs[col], sq1 = sqs[col + 1];
                #pragma unroll
                for (int mi = 0; mi < 2; mi++) {
                    int r0 = wm * 32 + mi * 16 + rq;
                    float* a4 = acc[mi][ni];
                    keys[r0 * KST + col]           = sq0 - 2.f * a4[0];
                    keys[r0 * KST + col + 1]       = sq1 - 2.f * a4[1];
                    keys[(r0 + 8) * KST + col]     = sq0 - 2.f * a4[2];
                    keys[(r0 + 8) * KST + col + 1] = sq1 - 2.f * a4[3];
                }
            }
            __syncthreads();
            // scan: threads t<128, (srow, sband) over 64 cols
            if (t < 128) {
                int jb = cbase + jt * 128 + sband * 64;
                const float* kr = &keys[srow * KST + sband * 64];
                #pragma unroll 4
                for (int c = 0; c < 64; c++) {
                    float v = kr[c];
                    if (v < wv) {
                        int pos = 0; float mv = tv[0];
                        #pragma unroll
                        for (int s = 1; s < NC; s++)
                            if (tv[s] > mv) { mv = tv[s]; pos = s; }
                        #pragma unroll
                        for (int s = 0; s < NC; s++)
                            if (s == pos) { tv[s] = v; ti[s] = jb + c; }
                        wv = tv[0];
                        #pragma unroll
                        for (int s = 1; s < NC; s++) wv = fmaxf(wv, tv[s]);
                    }
                }
            }
            // next iteration's top-of-loop __syncthreads protects keys reuse
        }
    }

    if (t < 128) {
        int row = rb + srow;
        #pragma unroll
        for (int s = 0; s < NC; s++)
            g_pi[row * 64 + half * 32 + sband * 16 + s] = ti[s];
    }
}

// ---------------- exact refine: 64 candidates -> top-10 ---------------------
__global__ __launch_bounds__(256) void refine_kernel() {
    __shared__ float fi[8][DD];
    int t = threadIdx.x, w = t >> 5, l = t & 31;
    int i = blockIdx.x * 8 + w;
    #pragma unroll
    for (int q = 0; q < 8; q++) fi[w][l + 32 * q] = g_f[i * DD + l + 32 * q];
    __syncwarp();
    int j0 = g_pi[i * 64 + l];
    int j1 = g_pi[i * 64 + 32 + l];
    const float4* f0 = (const float4*)&g_f[j0 * DD];
    const float4* f1 = (const float4*)&g_f[j1 * DD];
    float p0 = 0.f, p1 = 0.f, p2 = 0.f, p3 = 0.f;
    float q0 = 0.f, q1 = 0.f, q2 = 0.f, q3 = 0.f;
    #pragma unroll 8
    for (int k = 0; k < DD / 4; k++) {
        float4 v0 = f0[k], v1 = f1[k];
        float x0 = fi[w][4 * k], x1 = fi[w][4 * k + 1];
        float x2 = fi[w][4 * k + 2], x3 = fi[w][4 * k + 3];
        p0 = fmaf(x0, v0.x, p0); p1 = fmaf(x1, v0.y, p1);
        p2 = fmaf(x2, v0.z, p2); p3 = fmaf(x3, v0.w, p3);
        q0 = fmaf(x0, v1.x, q0); q1 = fmaf(x1, v1.y, q1);
        q2 = fmaf(x2, v1.z, q2); q3 = fmaf(x3, v1.w, q3);
    }
    float key0 = g_sq[j0] - 2.f * ((p0 + p1) + (p2 + p3));
    float key1 = g_sq[j1] - 2.f * ((q0 + q1) + (q2 + q3));
    unsigned kb0 = __float_as_uint(key0);
    kb0 = (kb0 & 0x80000000u) ? ~kb0 : (kb0 | 0x80000000u);
    unsigned kb1 = __float_as_uint(key1);
    kb1 = (kb1 & 0x80000000u) ? ~kb1 : (kb1 | 0x80000000u);
    unsigned long long pk0 = ((unsigned long long)kb0 << 32) | (unsigned)j0;
    unsigned long long pk1 = ((unsigned long long)kb1 << 32) | (unsigned)j1;
    #pragma unroll
    for (int r = 0; r < KNN; r++) {
        unsigned long long m = pk0 < pk1 ? pk0 : pk1;
        #pragma unroll
        for (int o = 16; o > 0; o >>= 1) {
            unsigned long long other = __shfl_xor_sync(0xffffffffu, m, o);
            if (other < m) m = other;
        }
        if (l == 0) g_idx[i * KNN + r] = (int)(m & 0xffffffffULL);
        if (pk0 == m) pk0 = 0xFFFFFFFFFFFFFFFFULL;
        else if (pk1 == m) pk1 = 0xFFFFFFFFFFFFFFFFULL;
    }
}

// ---------------- Laplacian apply -------------------------------------------
__global__ __launch_bounds__(256) void zero_kernel() {
    int tid = blockIdx.x * blockDim.x + threadIdx.x;
    int stride = gridDim.x * blockDim.x;
    float4 z4 = make_float4(0.f, 0.f, 0.f, 0.f);
    for (int i = tid; i < NP * DD / 4; i += stride) ((float4*)g_z)[i] = z4;
    if (tid < NP) g_bcnt[tid] = 0.f;
}

__global__ __launch_bounds__(256) void scatter_kernel(const float* __restrict__ x) {
    __shared__ int sidx[4][KNN];
    int t = threadIdx.x;
    int i0 = blockIdx.x * 4;
    if (t < 4 * KNN) {
        int r = t / KNN, k = t % KNN;
        int e = g_idx[(i0 + r) * KNN + k];
        sidx[r][k] = e;
        atomicAdd(&g_bcnt[e], 1.0f);
    }
    __syncthreads();
    int s = t >> 6;
    int cq = (t & 63) << 2;
    const float cnorm = 0.31622776601683794f;  // 1/sqrt(10+1e-10)
    float4 xv = *(const float4*)&x[(i0 + s) * DD + cq];
    float4 y = make_float4(xv.x * cnorm, xv.y * cnorm, xv.z * cnorm, xv.w * cnorm);
    #pragma unroll
    for (int k = 0; k < KNN; k++) {
        int e = sidx[s][k];
        float* p = &g_z[e * DD + cq];
        asm volatile("red.global.add.v4.f32 [%0], {%1, %2, %3, %4};"
                     :: "l"(p), "f"(y.x), "f"(y.y), "f"(y.z), "f"(y.w) : "memory");
    }
}

__global__ __launch_bounds__(256) void gather_kernel(const float* __restrict__ x) {
    __shared__ int   sidx[4][KNN];
    __shared__ float sbis[4][KNN];
    int t = threadIdx.x;
    int i0 = blockIdx.x * 4;
    if (t < 4 * KNN) {
        int r = t / KNN, k = t % KNN;
        int e = g_idx[(i0 + r) * KNN + k];
        sidx[r][k] = e;
        sbis[r][k] = 1.0f / sqrtf(g_bcnt[e] + 1e-10f);
    }
    __syncthreads();
    int s = t >> 6;
    int cq = (t & 63) << 2;
    float4 acc = make_float4(0.f, 0.f, 0.f, 0.f);
    #pragma unroll
    for (int k = 0; k < KNN; k++) {
        int e = sidx[s][k];
        float b = sbis[s][k];
        float4 zv = *(const float4*)&g_z[e * DD + cq];
        acc.x = fmaf(b, zv.x, acc.x);
        acc.y = fmaf(b, zv.y, acc.y);
        acc.z = fmaf(b, zv.z, acc.z);
        acc.w = fmaf(b, zv.w, acc.w);
    }
    const float hc = 0.5f * 0.31622776601683794f;
    float4 xv = *(const float4*)&x[(i0 + s) * DD + cq];
    float4 h;
    h.x = xv.x - hc * acc.x;
    h.y = xv.y - hc * acc.y;
    h.z = xv.z - hc * acc.z;
    h.w = xv.w - hc * acc.w;
    *(float4*)&g_h[(i0 + s) * DD + cq] = h;
}

// ---------------- launch -----------------------------------------------------
extern "C" void kernel_launch(void* const* d_in, const int* in_sizes, int n_in,
                              void* d_out, int out_size) {
    const float* x    = (const float*)d_in[0];   // (8192, 256)
    const float* w    = (const float*)d_in[1];   // (256, 256)
    const float* wd   = (const float*)d_in[2];   // (256, 256)
    const float* bias = (const float*)d_in[3];   // (256,)
    float* out = (float*)d_out;                  // (8192, 256)

    const int KNN_SMEM = 65536 + 64 * KST * 4 + 512;   // A+2B + keys + sqs = 99072
    cudaFuncSetAttribute(knn_coarse_kernel,
                         cudaFuncAttributeMaxDynamicSharedMemorySize, KNN_SMEM);

    gemm_f_kernel<<<dim3(DD / 64, NP / 64), 256>>>(x, wd);
    sqnorm_kernel<<<NP / 8, 256>>>();
    zero_kernel<<<1024, 256>>>();
    knn_coarse_kernel<<<dim3(2, NP / 64), 256, KNN_SMEM>>>();
    refine_kernel<<<NP / 8, 256>>>();
    scatter_kernel<<<NP / 4, 256>>>(x);
    gather_kernel<<<NP / 4, 256>>>(x);
    gemm_out_kernel<<<dim3(DD / 64, NP / 64), 256>>>(w, bias, out);
}

// round 8
// speedup vs baseline: 5.8111x; 1.7478x over previous
#include <cuda_runtime.h>
#include <cuda_bf16.h>
#include <cstdint>
#include <math.h>

#define NP  8192
#define DD  256
#define KNN 10
#define CAP 65        // push-buffer entries per row (u64)
#define TOPK 16       // per-(row,half) survivors
#define TOPST 17      // topk row stride in u64 (bank-spread)

// ---------------- scratch (static device globals; no allocation) ------------
__device__ float         g_f[NP * DD];    // f fp32 row-major
__device__ __nv_bfloat16 g_fb[NP * DD];   // f bf16 row-major
__device__ float         g_sq[NP];
__device__ int           g_pi[NP * 32];   // 32 candidates per row (2 halves x 16)
__device__ int           g_idx[NP * KNN];
__device__ float         g_z[NP * DD];
__device__ float         g_bcnt[NP];
__device__ float         g_h[NP * DD];

// ---------------- ptx helpers ------------------------------------------------
__device__ __forceinline__ uint32_t smem_u32(const void* p) {
    uint32_t a;
    asm("{ .reg .u64 t; cvta.to.shared.u64 t, %1; cvt.u32.u64 %0, t; }" : "=r"(a) : "l"(p));
    return a;
}
__device__ __forceinline__ void cpasync16(uint32_t dst, const void* src) {
    asm volatile("cp.async.cg.shared.global [%0], [%1], 16;" :: "r"(dst), "l"(src));
}
#define CP_COMMIT() asm volatile("cp.async.commit_group;" ::: "memory")
#define CP_WAIT0()  asm volatile("cp.async.wait_group 0;" ::: "memory")

__device__ __forceinline__ void ldsm_x4(uint32_t* r, uint32_t addr) {
    asm volatile("ldmatrix.sync.aligned.m8n8.x4.shared.b16 {%0,%1,%2,%3}, [%4];"
                 : "=r"(r[0]), "=r"(r[1]), "=r"(r[2]), "=r"(r[3]) : "r"(addr));
}
__device__ __forceinline__ void mma_bf16(float* c, const uint32_t* a,
                                         uint32_t b0, uint32_t b1) {
    asm volatile("mma.sync.aligned.m16n8k16.row.col.f32.bf16.bf16.f32 "
                 "{%0,%1,%2,%3}, {%4,%5,%6,%7}, {%8,%9}, {%0,%1,%2,%3};"
                 : "+f"(c[0]), "+f"(c[1]), "+f"(c[2]), "+f"(c[3])
                 : "r"(a[0]), "r"(a[1]), "r"(a[2]), "r"(a[3]), "r"(b0), "r"(b1));
}
__device__ __forceinline__ uint32_t fkey_map(float k) {
    uint32_t u = __float_as_uint(k);
    return (u & 0x80000000u) ? ~u : (u | 0x80000000u);
}
__device__ __forceinline__ float fkey_unmap(uint32_t m) {
    uint32_t u = (m & 0x80000000u) ? (m & 0x7fffffffu) : ~m;
    return __uint_as_float(u);
}

// ---------------- GEMM 1: g_f = x @ Wd (fp32) + g_fb (bf16) -----------------
__global__ __launch_bounds__(256) void gemm_f_kernel(const float* __restrict__ A,
                                                     const float* __restrict__ B) {
    __shared__ float As[16][64];
    __shared__ float Bs[16][64];
    int t  = threadIdx.x;
    int tx = t % 16, ty = t / 16;
    int rb = blockIdx.y * 64, cb = blockIdx.x * 64;
    float acc[4][4] = {};
    for (int k0 = 0; k0 < DD; k0 += 16) {
        {
            int row = t >> 2, kq = (t & 3) * 4;
            float4 v = *(const float4*)&A[(rb + row) * DD + k0 + kq];
            As[kq + 0][row] = v.x; As[kq + 1][row] = v.y;
            As[kq + 2][row] = v.z; As[kq + 3][row] = v.w;
        }
        {
            int krow = t >> 4, cq = (t & 15) * 4;
            *(float4*)&Bs[krow][cq] = *(const float4*)&B[(k0 + krow) * DD + cb + cq];
        }
        __syncthreads();
        #pragma unroll
        for (int kk = 0; kk < 16; kk++) {
            float4 av = *(const float4*)&As[kk][ty * 4];
            float4 bv = *(const float4*)&Bs[kk][tx * 4];
            float a[4] = {av.x, av.y, av.z, av.w};
            float b[4] = {bv.x, bv.y, bv.z, bv.w};
            #pragma unroll
            for (int i = 0; i < 4; i++)
                #pragma unroll
                for (int j = 0; j < 4; j++)
                    acc[i][j] = fmaf(a[i], b[j], acc[i][j]);
        }
        __syncthreads();
    }
    #pragma unroll
    for (int i = 0; i < 4; i++) {
        int r = rb + ty * 4 + i;
        int c = cb + tx * 4;
        float4 vv = make_float4(acc[i][0], acc[i][1], acc[i][2], acc[i][3]);
        *(float4*)&g_f[r * DD + c] = vv;
        __nv_bfloat162 b01 = __floats2bfloat162_rn(vv.x, vv.y);
        __nv_bfloat162 b23 = __floats2bfloat162_rn(vv.z, vv.w);
        uint2 pk;
        pk.x = *(uint32_t*)&b01;
        pk.y = *(uint32_t*)&b23;
        *(uint2*)&g_fb[r * DD + c] = pk;
    }
}

// ---------------- GEMM 2: out = h @ W + bias --------------------------------
__global__ __launch_bounds__(256) void gemm_out_kernel(const float* __restrict__ B,
                                                       const float* __restrict__ bias,
                                                       float* __restrict__ C) {
    __shared__ float As[16][64];
    __shared__ float Bs[16][64];
    int t  = threadIdx.x;
    int tx = t % 16, ty = t / 16;
    int rb = blockIdx.y * 64, cb = blockIdx.x * 64;
    const float* A = g_h;
    float acc[4][4] = {};
    for (int k0 = 0; k0 < DD; k0 += 16) {
        {
            int row = t >> 2, kq = (t & 3) * 4;
            float4 v = *(const float4*)&A[(rb + row) * DD + k0 + kq];
            As[kq + 0][row] = v.x; As[kq + 1][row] = v.y;
            As[kq + 2][row] = v.z; As[kq + 3][row] = v.w;
        }
        {
            int krow = t >> 4, cq = (t & 15) * 4;
            *(float4*)&Bs[krow][cq] = *(const float4*)&B[(k0 + krow) * DD + cb + cq];
        }
        __syncthreads();
        #pragma unroll
        for (int kk = 0; kk < 16; kk++) {
            float4 av = *(const float4*)&As[kk][ty * 4];
            float4 bv = *(const float4*)&Bs[kk][tx * 4];
            float a[4] = {av.x, av.y, av.z, av.w};
            float b[4] = {bv.x, bv.y, bv.z, bv.w};
            #pragma unroll
            for (int i = 0; i < 4; i++)
                #pragma unroll
                for (int j = 0; j < 4; j++)
                    acc[i][j] = fmaf(a[i], b[j], acc[i][j]);
        }
        __syncthreads();
    }
    #pragma unroll
    for (int i = 0; i < 4; i++) {
        int r = rb + ty * 4 + i;
        #pragma unroll
        for (int j = 0; j < 4; j++) {
            int c = cb + tx * 4 + j;
            C[r * DD + c] = acc[i][j] + bias[c];
        }
    }
}

// ---------------- row squared norms of f ------------------------------------
__global__ __launch_bounds__(256) void sqnorm_kernel() {
    int w = threadIdx.x >> 5, lane = threadIdx.x & 31;
    int row = blockIdx.x * 8 + w;
    const float* fr = &g_f[row * DD];
    float s = 0.f;
    #pragma unroll
    for (int q = 0; q < 8; q++) { float v = fr[lane + 32 * q]; s = fmaf(v, v, s); }
    #pragma unroll
    for (int o = 16; o > 0; o >>= 1) s += __shfl_xor_sync(0xffffffffu, s, o);
    if (lane == 0) g_sq[row] = s;
}

// ---------------- coarse knn: mma.sync bf16 + threshold filter --------------
// CTA: 64 rows x one 4096-col half, 2 CTAs/SM. Keys computed in registers
// from MMA accumulators; survivors (key < per-row threshold) pushed into a
// per-row smem buffer; per-row top-16 consolidated at geometric windows
// (jt = 0,1,3,7,15,31; the jt=31 pass is the final one before emit).
__global__ __launch_bounds__(256, 2) void knn_coarse_kernel() {
    extern __shared__ char dsm[];
    // layout: A 32768 | B0 16384 | B1 16384 | buf 33280 | topk 8704 |
    //         sqs 512 | cnt 256 | wvv 256   (total 108544)
    unsigned long long* buf  = (unsigned long long*)(dsm + 65536);
    unsigned long long* topk = (unsigned long long*)(dsm + 98816);
    float* sqs = (float*)(dsm + 107520);
    int*   cnt = (int*)(dsm + 108032);
    float* wvv = (float*)(dsm + 108288);

    int t = threadIdx.x, lane = t & 31, warp = t >> 5;
    int wm = warp & 1, wn = warp >> 1;
    int rb = blockIdx.y * 64;
    int half = blockIdx.x;
    int cbase = half * (NP / 2);

    uint32_t Abase  = smem_u32(dsm);
    uint32_t Bbase0 = Abase + 32768;
    uint32_t Bbase1 = Abase + 49152;

    const float INF = __int_as_float(0x7f800000);

    // init per-row structures
    if (t < 64) {
        #pragma unroll
        for (int k = 0; k < TOPK; k++) topk[t * TOPST + k] = ~0ULL;
        cnt[t] = 0;
        wvv[t] = INF;
    }

    // A tile (64 rows x 256 k), granule-swizzled: g' = g ^ (row&7)
    #pragma unroll
    for (int i = 0; i < 8; i++) {
        int idx = t + 256 * i;
        int id = idx >> 5, g = idx & 31;
        cpasync16(Abase + id * 512 + ((g ^ (id & 7)) << 4),
                  &g_fb[(rb + id) * DD + g * 8]);
    }
    // B chunk 0: 128 ids x 64 k
    #pragma unroll
    for (int i = 0; i < 4; i++) {
        int idx = t + 256 * i;
        int id = idx >> 3, g = idx & 7;
        cpasync16(Bbase0 + id * 128 + ((g ^ (id & 7)) << 4),
                  &g_fb[(cbase + id) * DD + g * 8]);
    }
    CP_COMMIT();

    // per-thread ldmatrix addressing (same fragment mapping as R5/R6)
    int arow = wm * 32 + (lane & 7) + ((lane & 8) ? 8 : 0);
    uint32_t Arow0 = Abase + arow * 512;
    uint32_t Arow1 = Arow0 + 16 * 512;
    int sw  = lane & 7;
    int aka = (lane & 16) ? 1 : 0;                   // A: k +8 selector
    int bro = (lane & 7) + ((lane & 16) ? 8 : 0);    // B: n-row within pair
    int bka = (lane & 8) ? 1 : 0;                    // B: k +8 selector

    int rq = lane >> 2, cq2 = (lane & 3) * 2;
    // rows owned by this thread's accumulators: wm*32 + mi*16 + qh*8 + rq
    float wvreg[4] = {INF, INF, INF, INF};           // [mi*2+qh]

    float acc[2][4][4];

    for (int cc = 0; cc < 128; cc++) {
        int jt = cc >> 2, kc = cc & 3;
        CP_WAIT0();
        __syncthreads();

        if (kc == 0 && t < 128) sqs[t] = g_sq[cbase + jt * 128 + t];

        // prefetch next chunk into the other buffer
        if (cc + 1 < 128) {
            int jn = (cc + 1) >> 2, kn = (cc + 1) & 3;
            uint32_t bb = ((cc + 1) & 1) ? Bbase1 : Bbase0;
            const __nv_bfloat16* src = &g_fb[(cbase + jn * 128) * DD + kn * 64];
            #pragma unroll
            for (int i = 0; i < 4; i++) {
                int idx = t + 256 * i;
                int id = idx >> 3, g = idx & 7;
                cpasync16(bb + id * 128 + ((g ^ (id & 7)) << 4), src + id * DD + g * 8);
            }
            CP_COMMIT();
        }

        if (kc == 0) {
            #pragma unroll
            for (int mi = 0; mi < 2; mi++)
                #pragma unroll
                for (int ni = 0; ni < 4; ni++)
                    #pragma unroll
                    for (int q = 0; q < 4; q++) acc[mi][ni][q] = 0.f;
        }

        uint32_t Bb = (cc & 1) ? Bbase1 : Bbase0;
        #pragma unroll
        for (int s = 0; s < 4; s++) {                // 4 k16 steps / 64-k chunk
            int ga = kc * 8 + s * 2 + aka;
            uint32_t a0[4], a1[4];
            ldsm_x4(a0, Arow0 + ((ga ^ sw) << 4));
            ldsm_x4(a1, Arow1 + ((ga ^ sw) << 4));
            int gb = s * 2 + bka;
            #pragma unroll
            for (int pi = 0; pi < 2; pi++) {
                int nrow = wn * 32 + pi * 16 + bro;
                uint32_t b[4];
                ldsm_x4(b, Bb + nrow * 128 + ((gb ^ sw) << 4));
                mma_bf16(acc[0][pi * 2 + 0], a0, b[0], b[1]);
                mma_bf16(acc[0][pi * 2 + 1], a0, b[2], b[3]);
                mma_bf16(acc[1][pi * 2 + 0], a1, b[0], b[1]);
                mma_bf16(acc[1][pi * 2 + 1], a1, b[2], b[3]);
            }
        }

        if (kc == 3) {
            int jb = cbase + jt * 128;
            if (jt == 0) {
                // bootstrap: per-thread top-4 of its 8 cols per owned row
                #pragma unroll
                for (int mi = 0; mi < 2; mi++)
                    #pragma unroll
                    for (int qh = 0; qh < 2; qh++) {
                        int rl = wm * 32 + mi * 16 + qh * 8 + rq;
                        float bv[4] = {INF, INF, INF, INF};
                        int bc[4] = {0, 0, 0, 0};
                        #pragma unroll
                        for (int ni = 0; ni < 4; ni++)
                            #pragma unroll
                            for (int ql = 0; ql < 2; ql++) {
                                int cl = wn * 32 + ni * 8 + cq2 + ql;
                                float k = fmaf(-2.f, acc[mi][ni][qh * 2 + ql], sqs[cl]);
                                if (k < bv[3]) {
                                    if (k < bv[2]) {
                                        bv[3] = bv[2]; bc[3] = bc[2];
                                        if (k < bv[1]) {
                                            bv[2] = bv[1]; bc[2] = bc[1];
                                            if (k < bv[0]) {
                                                bv[1] = bv[0]; bc[1] = bc[0];
                                                bv[0] = k; bc[0] = cl;
                                            } else { bv[1] = k; bc[1] = cl; }
                                        } else { bv[2] = k; bc[2] = cl; }
                                    } else { bv[3] = k; bc[3] = cl; }
                                }
                            }
                        #pragma unroll
                        for (int s2 = 0; s2 < 4; s2++) {
                            int pos = atomicAdd(&cnt[rl], 1);
                            if (pos < CAP)
                                buf[rl * CAP + pos] =
                                    ((unsigned long long)fkey_map(bv[s2]) << 32) |
                                    (unsigned)(jb + bc[s2]);
                        }
                    }
            } else {
                // threshold filter: push survivors only
                #pragma unroll
                for (int mi = 0; mi < 2; mi++)
                    #pragma unroll
                    for (int qh = 0; qh < 2; qh++) {
                        float wv = wvreg[mi * 2 + qh];
                        int rl = wm * 32 + mi * 16 + qh * 8 + rq;
                        #pragma unroll
                        for (int ni = 0; ni < 4; ni++)
                            #pragma unroll
                            for (int ql = 0; ql < 2; ql++) {
                                int cl = wn * 32 + ni * 8 + cq2 + ql;
                                float k = fmaf(-2.f, acc[mi][ni][qh * 2 + ql], sqs[cl]);
                                if (k < wv) {
                                    int pos = atomicAdd(&cnt[rl], 1);
                                    if (pos < CAP)
                                        buf[rl * CAP + pos] =
                                            ((unsigned long long)fkey_map(k) << 32) |
                                            (unsigned)(jb + cl);
                                }
                            }
                    }
            }

            if ((jt & (jt + 1)) == 0) {   // window boundary: jt = 2^m - 1
                __syncthreads();
                if (t < 64) {
                    int n = cnt[t]; if (n > CAP) n = CAP;
                    unsigned long long* tk = &topk[t * TOPST];
                    for (int e = 0; e < n; e++) {
                        unsigned long long v = buf[t * CAP + e];
                        int pm = 0; unsigned long long mv = tk[0];
                        #pragma unroll
                        for (int k = 1; k < TOPK; k++)
                            if (tk[k] > mv) { mv = tk[k]; pm = k; }
                        if (v < mv) tk[pm] = v;
                    }
                    cnt[t] = 0;
                    unsigned long long mv = tk[0];
                    #pragma unroll
                    for (int k = 1; k < TOPK; k++)
                        if (tk[k] > mv) mv = tk[k];
                    wvv[t] = fkey_unmap((uint32_t)(mv >> 32));
                }
                __syncthreads();
                #pragma unroll
                for (int mi = 0; mi < 2; mi++)
                    #pragma unroll
                    for (int qh = 0; qh < 2; qh++)
                        wvreg[mi * 2 + qh] = wvv[wm * 32 + mi * 16 + qh * 8 + rq];
            }
        }
    }

    // emit 16 candidates per (row, half); jt=31 consolidation already ran
    if (t < 64) {
        int row = rb + t;
        #pragma unroll
        for (int s = 0; s < TOPK; s++)
            g_pi[row * 32 + half * 16 + s] =
                (int)(topk[t * TOPST + s] & 0xffffffffULL);
    }
}

// ---------------- exact refine: 32 candidates -> top-10 ---------------------
__global__ __launch_bounds__(256) void refine_kernel() {
    __shared__ float fi[8][DD];
    int t = threadIdx.x, w = t >> 5, l = t & 31;
    int i = blockIdx.x * 8 + w;
    #pragma unroll
    for (int q = 0; q < 8; q++) fi[w][l + 32 * q] = g_f[i * DD + l + 32 * q];
    __syncwarp();
    int j = g_pi[i * 32 + l];
    const float4* fj = (const float4*)&g_f[j * DD];
    float p0 = 0.f, p1 = 0.f, p2 = 0.f, p3 = 0.f;
    #pragma unroll 8
    for (int k = 0; k < DD / 4; k++) {
        float4 v = fj[k];
        p0 = fmaf(fi[w][4 * k + 0], v.x, p0);
        p1 = fmaf(fi[w][4 * k + 1], v.y, p1);
        p2 = fmaf(fi[w][4 * k + 2], v.z, p2);
        p3 = fmaf(fi[w][4 * k + 3], v.w, p3);
    }
    float key = g_sq[j] - 2.f * ((p0 + p1) + (p2 + p3));
    uint32_t kb = __float_as_uint(key);
    kb = (kb & 0x80000000u) ? ~kb : (kb | 0x80000000u);
    unsigned long long pk = ((unsigned long long)kb << 32) | (unsigned)j;
    #pragma unroll
    for (int r = 0; r < KNN; r++) {
        unsigned long long m = pk;
        #pragma unroll
        for (int o = 16; o > 0; o >>= 1) {
            unsigned long long other = __shfl_xor_sync(0xffffffffu, m, o);
            if (other < m) m = other;
        }
        if (l == 0) g_idx[i * KNN + r] = (int)(m & 0xffffffffULL);
        if (pk == m) pk = 0xFFFFFFFFFFFFFFFFULL;
    }
}

// ---------------- Laplacian apply -------------------------------------------
__global__ __launch_bounds__(256) void zero_kernel() {
    int tid = blockIdx.x * blockDim.x + threadIdx.x;
    int stride = gridDim.x * blockDim.x;
    float4 z4 = make_float4(0.f, 0.f, 0.f, 0.f);
    for (int i = tid; i < NP * DD / 4; i += stride) ((float4*)g_z)[i] = z4;
    if (tid < NP) g_bcnt[tid] = 0.f;
}

__global__ __launch_bounds__(256) void scatter_kernel(const float* __restrict__ x) {
    __shared__ int sidx[4][KNN];
    int t = threadIdx.x;
    int i0 = blockIdx.x * 4;
    if (t < 4 * KNN) {
        int r = t / KNN, k = t % KNN;
        int e = g_idx[(i0 + r) * KNN + k];
        sidx[r][k] = e;
        atomicAdd(&g_bcnt[e], 1.0f);
    }
    __syncthreads();
    int s = t >> 6;
    int cq = (t & 63) << 2;
    const float cnorm = 0.31622776601683794f;  // 1/sqrt(10+1e-10)
    float4 xv = *(const float4*)&x[(i0 + s) * DD + cq];
    float4 y = make_float4(xv.x * cnorm, xv.y * cnorm, xv.z * cnorm, xv.w * cnorm);
    #pragma unroll
    for (int k = 0; k < KNN; k++) {
        int e = sidx[s][k];
        float* p = &g_z[e * DD + cq];
        asm volatile("red.global.add.v4.f32 [%0], {%1, %2, %3, %4};"
                     :: "l"(p), "f"(y.x), "f"(y.y), "f"(y.z), "f"(y.w) : "memory");
    }
}

__global__ __launch_bounds__(256) void gather_kernel(const float* __restrict__ x) {
    __shared__ int   sidx[4][KNN];
    __shared__ float sbis[4][KNN];
    int t = threadIdx.x;
    int i0 = blockIdx.x * 4;
    if (t < 4 * KNN) {
        int r = t / KNN, k = t % KNN;
        int e = g_idx[(i0 + r) * KNN + k];
        sidx[r][k] = e;
        sbis[r][k] = 1.0f / sqrtf(g_bcnt[e] + 1e-10f);
    }
    __syncthreads();
    int s = t >> 6;
    int cq = (t & 63) << 2;
    float4 acc = make_float4(0.f, 0.f, 0.f, 0.f);
    #pragma unroll
    for (int k = 0; k < KNN; k++) {
        int e = sidx[s][k];
        float b = sbis[s][k];
        float4 zv = *(const float4*)&g_z[e * DD + cq];
        acc.x = fmaf(b, zv.x, acc.x);
        acc.y = fmaf(b, zv.y, acc.y);
        acc.z = fmaf(b, zv.z, acc.z);
        acc.w = fmaf(b, zv.w, acc.w);
    }
    const float hc = 0.5f * 0.31622776601683794f;
    float4 xv = *(const float4*)&x[(i0 + s) * DD + cq];
    float4 h;
    h.x = xv.x - hc * acc.x;
    h.y = xv.y - hc * acc.y;
    h.z = xv.z - hc * acc.z;
    h.w = xv.w - hc * acc.w;
    *(float4*)&g_h[(i0 + s) * DD + cq] = h;
}

// ---------------- launch -----------------------------------------------------
extern "C" void kernel_launch(void* const* d_in, const int* in_sizes, int n_in,
                              void* d_out, int out_size) {
    const float* x    = (const float*)d_in[0];   // (8192, 256)
    const float* w    = (const float*)d_in[1];   // (256, 256)
    const float* wd   = (const float*)d_in[2];   // (256, 256)
    const float* bias = (const float*)d_in[3];   // (256,)
    float* out = (float*)d_out;                  // (8192, 256)

    const int KNN_SMEM = 108544;
    cudaFuncSetAttribute(knn_coarse_kernel,
                         cudaFuncAttributeMaxDynamicSharedMemorySize, KNN_SMEM);

    gemm_f_kernel<<<dim3(DD / 64, NP / 64), 256>>>(x, wd);
    sqnorm_kernel<<<NP / 8, 256>>>();
    zero_kernel<<<1024, 256>>>();
    knn_coarse_kernel<<<dim3(2, NP / 64), 256, KNN_SMEM>>>();
    refine_kernel<<<NP / 8, 256>>>();
    scatter_kernel<<<NP / 4, 256>>>(x);
    gather_kernel<<<NP / 4, 256>>>(x);
    gemm_out_kernel<<<dim3(DD / 64, NP / 64), 256>>>(w, bias, out);
}

// round 9
// speedup vs baseline: 5.8315x; 1.0035x over previous
#include <cuda_runtime.h>
#include <cuda_bf16.h>
#include <cstdint>
#include <math.h>

#define NP  8192
#define DD  256
#define KNN 10
#define CAP 65        // push-buffer entries per row (u64)
#define TOPK 16       // per-(row,half) survivors
#define TOPST 17      // topk row stride in u64 (bank-spread)

// ---------------- scratch (static device globals; no allocation) ------------
__device__ float         g_f[NP * DD];    // f fp32 row-major
__device__ __nv_bfloat16 g_fb[NP * DD];   // f bf16 row-major
__device__ float         g_sq[NP];
__device__ int           g_pi[NP * 32];   // 32 candidates per row (2 halves x 16)
__device__ int           g_idx[NP * KNN];
__device__ float         g_z[NP * DD];
__device__ float         g_bcnt[NP];
__device__ float         g_h[NP * DD];

// ---------------- ptx helpers ------------------------------------------------
__device__ __forceinline__ uint32_t smem_u32(const void* p) {
    uint32_t a;
    asm("{ .reg .u64 t; cvta.to.shared.u64 t, %1; cvt.u32.u64 %0, t; }" : "=r"(a) : "l"(p));
    return a;
}
__device__ __forceinline__ void cpasync16(uint32_t dst, const void* src) {
    asm volatile("cp.async.cg.shared.global [%0], [%1], 16;" :: "r"(dst), "l"(src));
}
#define CP_COMMIT() asm volatile("cp.async.commit_group;" ::: "memory")
#define CP_WAIT0()  asm volatile("cp.async.wait_group 0;" ::: "memory")

__device__ __forceinline__ void ldsm_x4(uint32_t* r, uint32_t addr) {
    asm volatile("ldmatrix.sync.aligned.m8n8.x4.shared.b16 {%0,%1,%2,%3}, [%4];"
                 : "=r"(r[0]), "=r"(r[1]), "=r"(r[2]), "=r"(r[3]) : "r"(addr));
}
__device__ __forceinline__ void mma_bf16(float* c, const uint32_t* a,
                                         uint32_t b0, uint32_t b1) {
    asm volatile("mma.sync.aligned.m16n8k16.row.col.f32.bf16.bf16.f32 "
                 "{%0,%1,%2,%3}, {%4,%5,%6,%7}, {%8,%9}, {%0,%1,%2,%3};"
                 : "+f"(c[0]), "+f"(c[1]), "+f"(c[2]), "+f"(c[3])
                 : "r"(a[0]), "r"(a[1]), "r"(a[2]), "r"(a[3]), "r"(b0), "r"(b1));
}
__device__ __forceinline__ uint32_t fkey_map(float k) {
    uint32_t u = __float_as_uint(k);
    return (u & 0x80000000u) ? ~u : (u | 0x80000000u);
}
__device__ __forceinline__ float fkey_unmap(uint32_t m) {
    uint32_t u = (m & 0x80000000u) ? (m & 0x7fffffffu) : ~m;
    return __uint_as_float(u);
}
// f32x2 packed fp32 (sm_100)
__device__ __forceinline__ unsigned long long pack2(float x, float y) {
    unsigned long long r;
    asm("mov.b64 %0, {%1, %2};" : "=l"(r) : "f"(x), "f"(y));
    return r;
}
__device__ __forceinline__ float2 unpack2(unsigned long long v) {
    float2 r;
    asm("mov.b64 {%0, %1}, %2;" : "=f"(r.x), "=f"(r.y) : "l"(v));
    return r;
}
#define FMA2(d, a, b) asm("fma.rn.f32x2 %0, %1, %2, %0;" : "+l"(d) : "l"(a), "l"(b))

// ---------------- GEMM 1: g_f = x @ Wd (fp32) + g_fb (bf16) + g_sq ----------
__global__ __launch_bounds__(256) void gemm_f_kernel(const float* __restrict__ A,
                                                     const float* __restrict__ B) {
    __shared__ float As[16][64];
    __shared__ float Bs[16][64];
    int t  = threadIdx.x;
    int tx = t % 16, ty = t / 16;
    int rb = blockIdx.y * 64, cb = blockIdx.x * 64;
    unsigned long long accp[4][2] = {};
    for (int k0 = 0; k0 < DD; k0 += 16) {
        {
            int row = t >> 2, kq = (t & 3) * 4;
            float4 v = *(const float4*)&A[(rb + row) * DD + k0 + kq];
            As[kq + 0][row] = v.x; As[kq + 1][row] = v.y;
            As[kq + 2][row] = v.z; As[kq + 3][row] = v.w;
        }
        {
            int krow = t >> 4, cq = (t & 15) * 4;
            *(float4*)&Bs[krow][cq] = *(const float4*)&B[(k0 + krow) * DD + cb + cq];
        }
        __syncthreads();
        #pragma unroll
        for (int kk = 0; kk < 16; kk++) {
            float4 av = *(const float4*)&As[kk][ty * 4];
            float4 bv = *(const float4*)&Bs[kk][tx * 4];
            unsigned long long bb0 = pack2(bv.x, bv.y);
            unsigned long long bb1 = pack2(bv.z, bv.w);
            float a[4] = {av.x, av.y, av.z, av.w};
            #pragma unroll
            for (int i = 0; i < 4; i++) {
                unsigned long long aa = pack2(a[i], a[i]);
                FMA2(accp[i][0], aa, bb0);
                FMA2(accp[i][1], aa, bb1);
            }
        }
        __syncthreads();
    }
    int lane = t & 31;
    #pragma unroll
    for (int i = 0; i < 4; i++) {
        int r = rb + ty * 4 + i;
        int c = cb + tx * 4;
        float2 u0 = unpack2(accp[i][0]);
        float2 u1 = unpack2(accp[i][1]);
        float4 vv = make_float4(u0.x, u0.y, u1.x, u1.y);
        *(float4*)&g_f[r * DD + c] = vv;
        __nv_bfloat162 b01 = __floats2bfloat162_rn(vv.x, vv.y);
        __nv_bfloat162 b23 = __floats2bfloat162_rn(vv.z, vv.w);
        uint2 pk;
        pk.x = *(uint32_t*)&b01;
        pk.y = *(uint32_t*)&b23;
        *(uint2*)&g_fb[r * DD + c] = pk;
        // fused sq-norm partial: reduce over the 16-thread tx group
        float sqp = vv.x * vv.x + vv.y * vv.y + vv.z * vv.z + vv.w * vv.w;
        #pragma unroll
        for (int o = 8; o > 0; o >>= 1)
            sqp += __shfl_xor_sync(0xffffffffu, sqp, o);
        if ((lane & 15) == 0) atomicAdd(&g_sq[r], sqp);
    }
}

// ---------------- GEMM 2: out = h @ W + bias --------------------------------
__global__ __launch_bounds__(256) void gemm_out_kernel(const float* __restrict__ B,
                                                       const float* __restrict__ bias,
                                                       float* __restrict__ C) {
    __shared__ float As[16][64];
    __shared__ float Bs[16][64];
    int t  = threadIdx.x;
    int tx = t % 16, ty = t / 16;
    int rb = blockIdx.y * 64, cb = blockIdx.x * 64;
    const float* A = g_h;
    unsigned long long accp[4][2] = {};
    for (int k0 = 0; k0 < DD; k0 += 16) {
        {
            int row = t >> 2, kq = (t & 3) * 4;
            float4 v = *(const float4*)&A[(rb + row) * DD + k0 + kq];
            As[kq + 0][row] = v.x; As[kq + 1][row] = v.y;
            As[kq + 2][row] = v.z; As[kq + 3][row] = v.w;
        }
        {
            int krow = t >> 4, cq = (t & 15) * 4;
            *(float4*)&Bs[krow][cq] = *(const float4*)&B[(k0 + krow) * DD + cb + cq];
        }
        __syncthreads();
        #pragma unroll
        for (int kk = 0; kk < 16; kk++) {
            float4 av = *(const float4*)&As[kk][ty * 4];
            float4 bv = *(const float4*)&Bs[kk][tx * 4];
            unsigned long long bb0 = pack2(bv.x, bv.y);
            unsigned long long bb1 = pack2(bv.z, bv.w);
            float a[4] = {av.x, av.y, av.z, av.w};
            #pragma unroll
            for (int i = 0; i < 4; i++) {
                unsigned long long aa = pack2(a[i], a[i]);
                FMA2(accp[i][0], aa, bb0);
                FMA2(accp[i][1], aa, bb1);
            }
        }
        __syncthreads();
    }
    #pragma unroll
    for (int i = 0; i < 4; i++) {
        int r = rb + ty * 4 + i;
        int c = cb + tx * 4;
        float2 u0 = unpack2(accp[i][0]);
        float2 u1 = unpack2(accp[i][1]);
        C[r * DD + c + 0] = u0.x + bias[c + 0];
        C[r * DD + c + 1] = u0.y + bias[c + 1];
        C[r * DD + c + 2] = u1.x + bias[c + 2];
        C[r * DD + c + 3] = u1.y + bias[c + 3];
    }
}

// ---------------- coarse knn: mma.sync bf16 + threshold filter --------------
// CTA: 64 rows x one 4096-col half, 2 CTAs/SM. Keys computed in registers
// from MMA accumulators; survivors (key < per-row threshold) pushed into a
// per-row smem buffer; per-row top-16 consolidated at geometric windows
// (jt = 0,1,3,7,15,31; the jt=31 pass is the final one before emit).
__global__ __launch_bounds__(256, 2) void knn_coarse_kernel() {
    extern __shared__ char dsm[];
    // layout: A 32768 | B0 16384 | B1 16384 | buf 33280 | topk 8704 |
    //         sqs 512 | cnt 256 | wvv 256   (total 108544)
    unsigned long long* buf  = (unsigned long long*)(dsm + 65536);
    unsigned long long* topk = (unsigned long long*)(dsm + 98816);
    float* sqs = (float*)(dsm + 107520);
    int*   cnt = (int*)(dsm + 108032);
    float* wvv = (float*)(dsm + 108288);

    int t = threadIdx.x, lane = t & 31, warp = t >> 5;
    int wm = warp & 1, wn = warp >> 1;
    int rb = blockIdx.y * 64;
    int half = blockIdx.x;
    int cbase = half * (NP / 2);

    uint32_t Abase  = smem_u32(dsm);
    uint32_t Bbase0 = Abase + 32768;
    uint32_t Bbase1 = Abase + 49152;

    const float INF = __int_as_float(0x7f800000);

    // init per-row structures
    if (t < 64) {
        #pragma unroll
        for (int k = 0; k < TOPK; k++) topk[t * TOPST + k] = ~0ULL;
        cnt[t] = 0;
        wvv[t] = INF;
    }

    // A tile (64 rows x 256 k), granule-swizzled: g' = g ^ (row&7)
    #pragma unroll
    for (int i = 0; i < 8; i++) {
        int idx = t + 256 * i;
        int id = idx >> 5, g = idx & 31;
        cpasync16(Abase + id * 512 + ((g ^ (id & 7)) << 4),
                  &g_fb[(rb + id) * DD + g * 8]);
    }
    // B chunk 0: 128 ids x 64 k
    #pragma unroll
    for (int i = 0; i < 4; i++) {
        int idx = t + 256 * i;
        int id = idx >> 3, g = idx & 7;
        cpasync16(Bbase0 + id * 128 + ((g ^ (id & 7)) << 4),
                  &g_fb[(cbase + id) * DD + g * 8]);
    }
    CP_COMMIT();

    // per-thread ldmatrix addressing (same fragment mapping as R5/R6)
    int arow = wm * 32 + (lane & 7) + ((lane & 8) ? 8 : 0);
    uint32_t Arow0 = Abase + arow * 512;
    uint32_t Arow1 = Arow0 + 16 * 512;
    int sw  = lane & 7;
    int aka = (lane & 16) ? 1 : 0;                   // A: k +8 selector
    int bro = (lane & 7) + ((lane & 16) ? 8 : 0);    // B: n-row within pair
    int bka = (lane & 8) ? 1 : 0;                    // B: k +8 selector

    int rq = lane >> 2, cq2 = (lane & 3) * 2;
    // rows owned by this thread's accumulators: wm*32 + mi*16 + qh*8 + rq
    float wvreg[4] = {INF, INF, INF, INF};           // [mi*2+qh]

    float acc[2][4][4];

    for (int cc = 0; cc < 128; cc++) {
        int jt = cc >> 2, kc = cc & 3;
        CP_WAIT0();
        __syncthreads();

        if (kc == 0 && t < 128) sqs[t] = g_sq[cbase + jt * 128 + t];

        // prefetch next chunk into the other buffer
        if (cc + 1 < 128) {
            int jn = (cc + 1) >> 2, kn = (cc + 1) & 3;
            uint32_t bb = ((cc + 1) & 1) ? Bbase1 : Bbase0;
            const __nv_bfloat16* src = &g_fb[(cbase + jn * 128) * DD + kn * 64];
            #pragma unroll
            for (int i = 0; i < 4; i++) {
                int idx = t + 256 * i;
                int id = idx >> 3, g = idx & 7;
                cpasync16(bb + id * 128 + ((g ^ (id & 7)) << 4), src + id * DD + g * 8);
            }
            CP_COMMIT();
        }

        if (kc == 0) {
            #pragma unroll
            for (int mi = 0; mi < 2; mi++)
                #pragma unroll
                for (int ni = 0; ni < 4; ni++)
                    #pragma unroll
                    for (int q = 0; q < 4; q++) acc[mi][ni][q] = 0.f;
        }

        uint32_t Bb = (cc & 1) ? Bbase1 : Bbase0;
        #pragma unroll
        for (int s = 0; s < 4; s++) {                // 4 k16 steps / 64-k chunk
            int ga = kc * 8 + s * 2 + aka;
            uint32_t a0[4], a1[4];
            ldsm_x4(a0, Arow0 + ((ga ^ sw) << 4));
            ldsm_x4(a1, Arow1 + ((ga ^ sw) << 4));
            int gb = s * 2 + bka;
            #pragma unroll
            for (int pi = 0; pi < 2; pi++) {
                int nrow = wn * 32 + pi * 16 + bro;
                uint32_t b[4];
                ldsm_x4(b, Bb + nrow * 128 + ((gb ^ sw) << 4));
                mma_bf16(acc[0][pi * 2 + 0], a0, b[0], b[1]);
                mma_bf16(acc[0][pi * 2 + 1], a0, b[2], b[3]);
                mma_bf16(acc[1][pi * 2 + 0], a1, b[0], b[1]);
                mma_bf16(acc[1][pi * 2 + 1], a1, b[2], b[3]);
            }
        }

        if (kc == 3) {
            int jb = cbase + jt * 128;
            if (jt == 0) {
                // bootstrap: per-thread top-4 of its 8 cols per owned row
                #pragma unroll
                for (int mi = 0; mi < 2; mi++)
                    #pragma unroll
                    for (int qh = 0; qh < 2; qh++) {
                        int rl = wm * 32 + mi * 16 + qh * 8 + rq;
                        float bv[4] = {INF, INF, INF, INF};
                        int bc[4] = {0, 0, 0, 0};
                        #pragma unroll
                        for (int ni = 0; ni < 4; ni++)
                            #pragma unroll
                            for (int ql = 0; ql < 2; ql++) {
                                int cl = wn * 32 + ni * 8 + cq2 + ql;
                                float k = fmaf(-2.f, acc[mi][ni][qh * 2 + ql], sqs[cl]);
                                if (k < bv[3]) {
                                    if (k < bv[2]) {
                                        bv[3] = bv[2]; bc[3] = bc[2];
                                        if (k < bv[1]) {
                                            bv[2] = bv[1]; bc[2] = bc[1];
                                            if (k < bv[0]) {
                                                bv[1] = bv[0]; bc[1] = bc[0];
                                                bv[0] = k; bc[0] = cl;
                                            } else { bv[1] = k; bc[1] = cl; }
                                        } else { bv[2] = k; bc[2] = cl; }
                                    } else { bv[3] = k; bc[3] = cl; }
                                }
                            }
                        #pragma unroll
                        for (int s2 = 0; s2 < 4; s2++) {
                            int pos = atomicAdd(&cnt[rl], 1);
                            if (pos < CAP)
                                buf[rl * CAP + pos] =
                                    ((unsigned long long)fkey_map(bv[s2]) << 32) |
                                    (unsigned)(jb + bc[s2]);
                        }
                    }
            } else {
                // threshold filter: push survivors only
                #pragma unroll
                for (int mi = 0; mi < 2; mi++)
                    #pragma unroll
                    for (int qh = 0; qh < 2; qh++) {
                        float wv = wvreg[mi * 2 + qh];
                        int rl = wm * 32 + mi * 16 + qh * 8 + rq;
                        #pragma unroll
                        for (int ni = 0; ni < 4; ni++)
                            #pragma unroll
                            for (int ql = 0; ql < 2; ql++) {
                                int cl = wn * 32 + ni * 8 + cq2 + ql;
                                float k = fmaf(-2.f, acc[mi][ni][qh * 2 + ql], sqs[cl]);
                                if (k < wv) {
                                    int pos = atomicAdd(&cnt[rl], 1);
                                    if (pos < CAP)
                                        buf[rl * CAP + pos] =
                                            ((unsigned long long)fkey_map(k) << 32) |
                                            (unsigned)(jb + cl);
                                }
                            }
                    }
            }

            if ((jt & (jt + 1)) == 0) {   // window boundary: jt = 2^m - 1
                __syncthreads();
                if (t < 64) {
                    int n = cnt[t]; if (n > CAP) n = CAP;
                    unsigned long long* tk = &topk[t * TOPST];
                    for (int e = 0; e < n; e++) {
                        unsigned long long v = buf[t * CAP + e];
                        int pm = 0; unsigned long long mv = tk[0];
                        #pragma unroll
                        for (int k = 1; k < TOPK; k++)
                            if (tk[k] > mv) { mv = tk[k]; pm = k; }
                        if (v < mv) tk[pm] = v;
                    }
                    cnt[t] = 0;
                    unsigned long long mv = tk[0];
                    #pragma unroll
                    for (int k = 1; k < TOPK; k++)
                        if (tk[k] > mv) mv = tk[k];
                    wvv[t] = fkey_unmap((uint32_t)(mv >> 32));
                }
                __syncthreads();
                #pragma unroll
                for (int mi = 0; mi < 2; mi++)
                    #pragma unroll
                    for (int qh = 0; qh < 2; qh++)
                        wvreg[mi * 2 + qh] = wvv[wm * 32 + mi * 16 + qh * 8 + rq];
            }
        }
    }

    // emit 16 candidates per (row, half); jt=31 consolidation already ran
    if (t < 64) {
        int row = rb + t;
        #pragma unroll
        for (int s = 0; s < TOPK; s++)
            g_pi[row * 32 + half * 16 + s] =
                (int)(topk[t * TOPST + s] & 0xffffffffULL);
    }
}

// ---------------- exact refine: 32 candidates -> top-10 ---------------------
__global__ __launch_bounds__(256) void refine_kernel() {
    __shared__ float fi[8][DD];
    int t = threadIdx.x, w = t >> 5, l = t & 31;
    int i = blockIdx.x * 8 + w;
    #pragma unroll
    for (int q = 0; q < 8; q++) fi[w][l + 32 * q] = g_f[i * DD + l + 32 * q];
    __syncwarp();
    int j = g_pi[i * 32 + l];
    const float4* fj = (const float4*)&g_f[j * DD];
    float p0 = 0.f, p1 = 0.f, p2 = 0.f, p3 = 0.f;
    #pragma unroll 8
    for (int k = 0; k < DD / 4; k++) {
        float4 v = fj[k];
        p0 = fmaf(fi[w][4 * k + 0], v.x, p0);
        p1 = fmaf(fi[w][4 * k + 1], v.y, p1);
        p2 = fmaf(fi[w][4 * k + 2], v.z, p2);
        p3 = fmaf(fi[w][4 * k + 3], v.w, p3);
    }
    float key = g_sq[j] - 2.f * ((p0 + p1) + (p2 + p3));
    uint32_t kb = __float_as_uint(key);
    kb = (kb & 0x80000000u) ? ~kb : (kb | 0x80000000u);
    unsigned long long pk = ((unsigned long long)kb << 32) | (unsigned)j;
    #pragma unroll
    for (int r = 0; r < KNN; r++) {
        unsigned long long m = pk;
        #pragma unroll
        for (int o = 16; o > 0; o >>= 1) {
            unsigned long long other = __shfl_xor_sync(0xffffffffu, m, o);
            if (other < m) m = other;
        }
        if (l == 0) g_idx[i * KNN + r] = (int)(m & 0xffffffffULL);
        if (pk == m) pk = 0xFFFFFFFFFFFFFFFFULL;
    }
}

// ---------------- Laplacian apply -------------------------------------------
__global__ __launch_bounds__(256) void zero_kernel() {
    int tid = blockIdx.x * blockDim.x + threadIdx.x;
    int stride = gridDim.x * blockDim.x;
    float4 z4 = make_float4(0.f, 0.f, 0.f, 0.f);
    for (int i = tid; i < NP * DD / 4; i += stride) ((float4*)g_z)[i] = z4;
    if (tid < NP) { g_bcnt[tid] = 0.f; g_sq[tid] = 0.f; }
}

__global__ __launch_bounds__(256) void scatter_kernel(const float* __restrict__ x) {
    __shared__ int sidx[4][KNN];
    int t = threadIdx.x;
    int i0 = blockIdx.x * 4;
    if (t < 4 * KNN) {
        int r = t / KNN, k = t % KNN;
        int e = g_idx[(i0 + r) * KNN + k];
        sidx[r][k] = e;
        atomicAdd(&g_bcnt[e], 1.0f);
    }
    __syncthreads();
    int s = t >> 6;
    int cq = (t & 63) << 2;
    const float cnorm = 0.31622776601683794f;  // 1/sqrt(10+1e-10)
    float4 xv = *(const float4*)&x[(i0 + s) * DD + cq];
    float4 y = make_float4(xv.x * cnorm, xv.y * cnorm, xv.z * cnorm, xv.w * cnorm);
    #pragma unroll
    for (int k = 0; k < KNN; k++) {
        int e = sidx[s][k];
        float* p = &g_z[e * DD + cq];
        asm volatile("red.global.add.v4.f32 [%0], {%1, %2, %3, %4};"
                     :: "l"(p), "f"(y.x), "f"(y.y), "f"(y.z), "f"(y.w) : "memory");
    }
}

__global__ __launch_bounds__(256) void gather_kernel(const float* __restrict__ x) {
    __shared__ int   sidx[4][KNN];
    __shared__ float sbis[4][KNN];
    int t = threadIdx.x;
    int i0 = blockIdx.x * 4;
    if (t < 4 * KNN) {
        int r = t / KNN, k = t % KNN;
        int e = g_idx[(i0 + r) * KNN + k];
        sidx[r][k] = e;
        sbis[r][k] = 1.0f / sqrtf(g_bcnt[e] + 1e-10f);
    }
    __syncthreads();
    int s = t >> 6;
    int cq = (t & 63) << 2;
    float4 acc = make_float4(0.f, 0.f, 0.f, 0.f);
    #pragma unroll
    for (int k = 0; k < KNN; k++) {
        int e = sidx[s][k];
        float b = sbis[s][k];
        float4 zv = *(const float4*)&g_z[e * DD + cq];
        acc.x = fmaf(b, zv.x, acc.x);
        acc.y = fmaf(b, zv.y, acc.y);
        acc.z = fmaf(b, zv.z, acc.z);
        acc.w = fmaf(b, zv.w, acc.w);
    }
    const float hc = 0.5f * 0.31622776601683794f;
    float4 xv = *(const float4*)&x[(i0 + s) * DD + cq];
    float4 h;
    h.x = xv.x - hc * acc.x;
    h.y = xv.y - hc * acc.y;
    h.z = xv.z - hc * acc.z;
    h.w = xv.w - hc * acc.w;
    *(float4*)&g_h[(i0 + s) * DD + cq] = h;
}

// ---------------- launch -----------------------------------------------------
extern "C" void kernel_launch(void* const* d_in, const int* in_sizes, int n_in,
                              void* d_out, int out_size) {
    const float* x    = (const float*)d_in[0];   // (8192, 256)
    const float* w    = (const float*)d_in[1];   // (256, 256)
    const float* wd   = (const float*)d_in[2];   // (256, 256)
    const float* bias = (const float*)d_in[3];   // (256,)
    float* out = (float*)d_out;                  // (8192, 256)

    const int KNN_SMEM = 108544;
    cudaFuncSetAttribute(knn_coarse_kernel,
                         cudaFuncAttributeMaxDynamicSharedMemorySize, KNN_SMEM);

    zero_kernel<<<1024, 256>>>();                       // g_z, g_bcnt, g_sq = 0
    gemm_f_kernel<<<dim3(DD / 64, NP / 64), 256>>>(x, wd);  // f, fb, sq (fused)
    knn_coarse_kernel<<<dim3(2, NP / 64), 256, KNN_SMEM>>>();
    refine_kernel<<<NP / 8, 256>>>();
    scatter_kernel<<<NP / 4, 256>>>(x);
    gather_kernel<<<NP / 4, 256>>>(x);
    gemm_out_kernel<<<dim3(DD / 64, NP / 64), 256>>>(w, bias, out);
}

// round 10
// speedup vs baseline: 6.5052x; 1.1155x over previous
#include <cuda_runtime.h>
#include <cuda_bf16.h>
#include <cstdint>
#include <math.h>

#define NP  8192
#define DD  256
#define KNN 10
#define CAP 65        // push-buffer entries per row (u64)
#define TOPK 16       // per-(row,half) survivors
#define TOPST 17      // topk row stride in u64 (bank-spread)

// ---------------- scratch (static device globals; no allocation) ------------
__device__ float         g_f[NP * DD];    // f fp32 row-major
__device__ __nv_bfloat16 g_fb[NP * DD];   // f bf16 row-major
__device__ float         g_sq[NP];
__device__ int           g_pi[NP * 32];   // 32 candidates per row (2 halves x 16)
__device__ int           g_idx[NP * KNN];
__device__ float         g_z[NP * DD];
__device__ float         g_bcnt[NP];
__device__ float         g_h[NP * DD];

// ---------------- ptx helpers ------------------------------------------------
__device__ __forceinline__ uint32_t smem_u32(const void* p) {
    uint32_t a;
    asm("{ .reg .u64 t; cvta.to.shared.u64 t, %1; cvt.u32.u64 %0, t; }" : "=r"(a) : "l"(p));
    return a;
}
__device__ __forceinline__ void cpasync16(uint32_t dst, const void* src) {
    asm volatile("cp.async.cg.shared.global [%0], [%1], 16;" :: "r"(dst), "l"(src));
}
#define CP_COMMIT() asm volatile("cp.async.commit_group;" ::: "memory")
#define CP_WAIT0()  asm volatile("cp.async.wait_group 0;" ::: "memory")

__device__ __forceinline__ void ldsm_x4(uint32_t* r, uint32_t addr) {
    asm volatile("ldmatrix.sync.aligned.m8n8.x4.shared.b16 {%0,%1,%2,%3}, [%4];"
                 : "=r"(r[0]), "=r"(r[1]), "=r"(r[2]), "=r"(r[3]) : "r"(addr));
}
__device__ __forceinline__ void mma_bf16(float* c, const uint32_t* a,
                                         uint32_t b0, uint32_t b1) {
    asm volatile("mma.sync.aligned.m16n8k16.row.col.f32.bf16.bf16.f32 "
                 "{%0,%1,%2,%3}, {%4,%5,%6,%7}, {%8,%9}, {%0,%1,%2,%3};"
                 : "+f"(c[0]), "+f"(c[1]), "+f"(c[2]), "+f"(c[3])
                 : "r"(a[0]), "r"(a[1]), "r"(a[2]), "r"(a[3]), "r"(b0), "r"(b1));
}
__device__ __forceinline__ uint32_t fkey_map(float k) {
    uint32_t u = __float_as_uint(k);
    return (u & 0x80000000u) ? ~u : (u | 0x80000000u);
}
__device__ __forceinline__ float fkey_unmap(uint32_t m) {
    uint32_t u = (m & 0x80000000u) ? (m & 0x7fffffffu) : ~m;
    return __uint_as_float(u);
}
// f32x2 packed fp32 (sm_100)
__device__ __forceinline__ unsigned long long pack2(float x, float y) {
    unsigned long long r;
    asm("mov.b64 %0, {%1, %2};" : "=l"(r) : "f"(x), "f"(y));
    return r;
}
__device__ __forceinline__ float2 unpack2(unsigned long long v) {
    float2 r;
    asm("mov.b64 {%0, %1}, %2;" : "=f"(r.x), "=f"(r.y) : "l"(v));
    return r;
}
#define FMA2(d, a, b) asm("fma.rn.f32x2 %0, %1, %2, %0;" : "+l"(d) : "l"(a), "l"(b))

// ---------------- GEMM 1: g_f = x @ Wd (fp32) + g_fb (bf16) + g_sq ----------
__global__ __launch_bounds__(256) void gemm_f_kernel(const float* __restrict__ A,
                                                     const float* __restrict__ B) {
    __shared__ float As[16][64];
    __shared__ float Bs[16][64];
    int t  = threadIdx.x;
    int tx = t % 16, ty = t / 16;
    int rb = blockIdx.y * 64, cb = blockIdx.x * 64;
    unsigned long long accp[4][2] = {};
    for (int k0 = 0; k0 < DD; k0 += 16) {
        {
            int row = t >> 2, kq = (t & 3) * 4;
            float4 v = *(const float4*)&A[(rb + row) * DD + k0 + kq];
            As[kq + 0][row] = v.x; As[kq + 1][row] = v.y;
            As[kq + 2][row] = v.z; As[kq + 3][row] = v.w;
        }
        {
            int krow = t >> 4, cq = (t & 15) * 4;
            *(float4*)&Bs[krow][cq] = *(const float4*)&B[(k0 + krow) * DD + cb + cq];
        }
        __syncthreads();
        #pragma unroll
        for (int kk = 0; kk < 16; kk++) {
            float4 av = *(const float4*)&As[kk][ty * 4];
            float4 bv = *(const float4*)&Bs[kk][tx * 4];
            unsigned long long bb0 = pack2(bv.x, bv.y);
            unsigned long long bb1 = pack2(bv.z, bv.w);
            float a[4] = {av.x, av.y, av.z, av.w};
            #pragma unroll
            for (int i = 0; i < 4; i++) {
                unsigned long long aa = pack2(a[i], a[i]);
                FMA2(accp[i][0], aa, bb0);
                FMA2(accp[i][1], aa, bb1);
            }
        }
        __syncthreads();
    }
    int lane = t & 31;
    #pragma unroll
    for (int i = 0; i < 4; i++) {
        int r = rb + ty * 4 + i;
        int c = cb + tx * 4;
        float2 u0 = unpack2(accp[i][0]);
        float2 u1 = unpack2(accp[i][1]);
        float4 vv = make_float4(u0.x, u0.y, u1.x, u1.y);
        *(float4*)&g_f[r * DD + c] = vv;
        __nv_bfloat162 b01 = __floats2bfloat162_rn(vv.x, vv.y);
        __nv_bfloat162 b23 = __floats2bfloat162_rn(vv.z, vv.w);
        uint2 pk;
        pk.x = *(uint32_t*)&b01;
        pk.y = *(uint32_t*)&b23;
        *(uint2*)&g_fb[r * DD + c] = pk;
        // fused sq-norm partial: reduce over the 16-thread tx group
        float sqp = vv.x * vv.x + vv.y * vv.y + vv.z * vv.z + vv.w * vv.w;
        #pragma unroll
        for (int o = 8; o > 0; o >>= 1)
            sqp += __shfl_xor_sync(0xffffffffu, sqp, o);
        if ((lane & 15) == 0) atomicAdd(&g_sq[r], sqp);
    }
}

// ---------------- GEMM 2: out = h @ W + bias --------------------------------
__global__ __launch_bounds__(256) void gemm_out_kernel(const float* __restrict__ B,
                                                       const float* __restrict__ bias,
                                                       float* __restrict__ C) {
    __shared__ float As[16][64];
    __shared__ float Bs[16][64];
    int t  = threadIdx.x;
    int tx = t % 16, ty = t / 16;
    int rb = blockIdx.y * 64, cb = blockIdx.x * 64;
    const float* A = g_h;
    unsigned long long accp[4][2] = {};
    for (int k0 = 0; k0 < DD; k0 += 16) {
        {
            int row = t >> 2, kq = (t & 3) * 4;
            float4 v = *(const float4*)&A[(rb + row) * DD + k0 + kq];
            As[kq + 0][row] = v.x; As[kq + 1][row] = v.y;
            As[kq + 2][row] = v.z; As[kq + 3][row] = v.w;
        }
        {
            int krow = t >> 4, cq = (t & 15) * 4;
            *(float4*)&Bs[krow][cq] = *(const float4*)&B[(k0 + krow) * DD + cb + cq];
        }
        __syncthreads();
        #pragma unroll
        for (int kk = 0; kk < 16; kk++) {
            float4 av = *(const float4*)&As[kk][ty * 4];
            float4 bv = *(const float4*)&Bs[kk][tx * 4];
            unsigned long long bb0 = pack2(bv.x, bv.y);
            unsigned long long bb1 = pack2(bv.z, bv.w);
            float a[4] = {av.x, av.y, av.z, av.w};
            #pragma unroll
            for (int i = 0; i < 4; i++) {
                unsigned long long aa = pack2(a[i], a[i]);
                FMA2(accp[i][0], aa, bb0);
                FMA2(accp[i][1], aa, bb1);
            }
        }
        __syncthreads();
    }
    #pragma unroll
    for (int i = 0; i < 4; i++) {
        int r = rb + ty * 4 + i;
        int c = cb + tx * 4;
        float2 u0 = unpack2(accp[i][0]);
        float2 u1 = unpack2(accp[i][1]);
        C[r * DD + c + 0] = u0.x + bias[c + 0];
        C[r * DD + c + 1] = u0.y + bias[c + 1];
        C[r * DD + c + 2] = u1.x + bias[c + 2];
        C[r * DD + c + 3] = u1.y + bias[c + 3];
    }
}

// ---------------- coarse knn: mma.sync bf16 + threshold filter --------------
// CTA: 64 rows x one 4096-col half, 2 CTAs/SM. Keys computed in registers
// from MMA accumulators; survivors (key < per-row threshold) pushed into a
// per-row smem buffer; per-row top-16 consolidated at geometric windows
// (jt = 0,1,3,7,15,31; the jt=31 pass is the final one before emit).
__global__ __launch_bounds__(256, 2) void knn_coarse_kernel() {
    extern __shared__ char dsm[];
    // layout: A 32768 | B0 16384 | B1 16384 | buf 33280 | topk 8704 |
    //         sqs 512 | cnt 256 | wvv 256   (total 108544)
    unsigned long long* buf  = (unsigned long long*)(dsm + 65536);
    unsigned long long* topk = (unsigned long long*)(dsm + 98816);
    float* sqs = (float*)(dsm + 107520);
    int*   cnt = (int*)(dsm + 108032);
    float* wvv = (float*)(dsm + 108288);

    int t = threadIdx.x, lane = t & 31, warp = t >> 5;
    int wm = warp & 1, wn = warp >> 1;
    int rb = blockIdx.y * 64;
    int half = blockIdx.x;
    int cbase = half * (NP / 2);

    uint32_t Abase  = smem_u32(dsm);
    uint32_t Bbase0 = Abase + 32768;
    uint32_t Bbase1 = Abase + 49152;

    const float INF = __int_as_float(0x7f800000);

    // init per-row structures
    if (t < 64) {
        #pragma unroll
        for (int k = 0; k < TOPK; k++) topk[t * TOPST + k] = ~0ULL;
        cnt[t] = 0;
        wvv[t] = INF;
    }

    // A tile (64 rows x 256 k), granule-swizzled: g' = g ^ (row&7)
    #pragma unroll
    for (int i = 0; i < 8; i++) {
        int idx = t + 256 * i;
        int id = idx >> 5, g = idx & 31;
        cpasync16(Abase + id * 512 + ((g ^ (id & 7)) << 4),
                  &g_fb[(rb + id) * DD + g * 8]);
    }
    // B chunk 0: 128 ids x 64 k
    #pragma unroll
    for (int i = 0; i < 4; i++) {
        int idx = t + 256 * i;
        int id = idx >> 3, g = idx & 7;
        cpasync16(Bbase0 + id * 128 + ((g ^ (id & 7)) << 4),
                  &g_fb[(cbase + id) * DD + g * 8]);
    }
    CP_COMMIT();

    // per-thread ldmatrix addressing (same fragment mapping as R5/R6)
    int arow = wm * 32 + (lane & 7) + ((lane & 8) ? 8 : 0);
    uint32_t Arow0 = Abase + arow * 512;
    uint32_t Arow1 = Arow0 + 16 * 512;
    int sw  = lane & 7;
    int aka = (lane & 16) ? 1 : 0;                   // A: k +8 selector
    int bro = (lane & 7) + ((lane & 16) ? 8 : 0);    // B: n-row within pair
    int bka = (lane & 8) ? 1 : 0;                    // B: k +8 selector

    int rq = lane >> 2, cq2 = (lane & 3) * 2;
    // rows owned by this thread's accumulators: wm*32 + mi*16 + qh*8 + rq
    float wvreg[4] = {INF, INF, INF, INF};           // [mi*2+qh]

    float acc[2][4][4];

    for (int cc = 0; cc < 128; cc++) {
        int jt = cc >> 2, kc = cc & 3;
        CP_WAIT0();
        __syncthreads();

        if (kc == 0 && t < 128) sqs[t] = g_sq[cbase + jt * 128 + t];

        // prefetch next chunk into the other buffer
        if (cc + 1 < 128) {
            int jn = (cc + 1) >> 2, kn = (cc + 1) & 3;
            uint32_t bb = ((cc + 1) & 1) ? Bbase1 : Bbase0;
            const __nv_bfloat16* src = &g_fb[(cbase + jn * 128) * DD + kn * 64];
            #pragma unroll
            for (int i = 0; i < 4; i++) {
                int idx = t + 256 * i;
                int id = idx >> 3, g = idx & 7;
                cpasync16(bb + id * 128 + ((g ^ (id & 7)) << 4), src + id * DD + g * 8);
            }
            CP_COMMIT();
        }

        if (kc == 0) {
            #pragma unroll
            for (int mi = 0; mi < 2; mi++)
                #pragma unroll
                for (int ni = 0; ni < 4; ni++)
                    #pragma unroll
                    for (int q = 0; q < 4; q++) acc[mi][ni][q] = 0.f;
        }

        uint32_t Bb = (cc & 1) ? Bbase1 : Bbase0;
        #pragma unroll
        for (int s = 0; s < 4; s++) {                // 4 k16 steps / 64-k chunk
            int ga = kc * 8 + s * 2 + aka;
            uint32_t a0[4], a1[4];
            ldsm_x4(a0, Arow0 + ((ga ^ sw) << 4));
            ldsm_x4(a1, Arow1 + ((ga ^ sw) << 4));
            int gb = s * 2 + bka;
            #pragma unroll
            for (int pi = 0; pi < 2; pi++) {
                int nrow = wn * 32 + pi * 16 + bro;
                uint32_t b[4];
                ldsm_x4(b, Bb + nrow * 128 + ((gb ^ sw) << 4));
                mma_bf16(acc[0][pi * 2 + 0], a0, b[0], b[1]);
                mma_bf16(acc[0][pi * 2 + 1], a0, b[2], b[3]);
                mma_bf16(acc[1][pi * 2 + 0], a1, b[0], b[1]);
                mma_bf16(acc[1][pi * 2 + 1], a1, b[2], b[3]);
            }
        }

        if (kc == 3) {
            int jb = cbase + jt * 128;
            if (jt == 0) {
                // bootstrap: per-thread top-4 of its 8 cols per owned row
                #pragma unroll
                for (int mi = 0; mi < 2; mi++)
                    #pragma unroll
                    for (int qh = 0; qh < 2; qh++) {
                        int rl = wm * 32 + mi * 16 + qh * 8 + rq;
                        float bv[4] = {INF, INF, INF, INF};
                        int bc[4] = {0, 0, 0, 0};
                        #pragma unroll
                        for (int ni = 0; ni < 4; ni++)
                            #pragma unroll
                            for (int ql = 0; ql < 2; ql++) {
                                int cl = wn * 32 + ni * 8 + cq2 + ql;
                                float k = fmaf(-2.f, acc[mi][ni][qh * 2 + ql], sqs[cl]);
                                if (k < bv[3]) {
                                    if (k < bv[2]) {
                                        bv[3] = bv[2]; bc[3] = bc[2];
                                        if (k < bv[1]) {
                                            bv[2] = bv[1]; bc[2] = bc[1];
                                            if (k < bv[0]) {
                                                bv[1] = bv[0]; bc[1] = bc[0];
                                                bv[0] = k; bc[0] = cl;
                                            } else { bv[1] = k; bc[1] = cl; }
                                        } else { bv[2] = k; bc[2] = cl; }
                                    } else { bv[3] = k; bc[3] = cl; }
                                }
                            }
                        #pragma unroll
                        for (int s2 = 0; s2 < 4; s2++) {
                            int pos = atomicAdd(&cnt[rl], 1);
                            if (pos < CAP)
                                buf[rl * CAP + pos] =
                                    ((unsigned long long)fkey_map(bv[s2]) << 32) |
                                    (unsigned)(jb + bc[s2]);
                        }
                    }
            } else {
                // threshold filter: push survivors only
                #pragma unroll
                for (int mi = 0; mi < 2; mi++)
                    #pragma unroll
                    for (int qh = 0; qh < 2; qh++) {
                        float wv = wvreg[mi * 2 + qh];
                        int rl = wm * 32 + mi * 16 + qh * 8 + rq;
                        #pragma unroll
                        for (int ni = 0; ni < 4; ni++)
                            #pragma unroll
                            for (int ql = 0; ql < 2; ql++) {
                                int cl = wn * 32 + ni * 8 + cq2 + ql;
                                float k = fmaf(-2.f, acc[mi][ni][qh * 2 + ql], sqs[cl]);
                                if (k < wv) {
                                    int pos = atomicAdd(&cnt[rl], 1);
                                    if (pos < CAP)
                                        buf[rl * CAP + pos] =
                                            ((unsigned long long)fkey_map(k) << 32) |
                                            (unsigned)(jb + cl);
                                }
                            }
                    }
            }

            if ((jt & (jt + 1)) == 0) {   // window boundary: jt = 2^m - 1
                __syncthreads();
                if (t < 64) {
                    int n = cnt[t]; if (n > CAP) n = CAP;
                    unsigned long long* tk = &topk[t * TOPST];
                    for (int e = 0; e < n; e++) {
                        unsigned long long v = buf[t * CAP + e];
                        int pm = 0; unsigned long long mv = tk[0];
                        #pragma unroll
                        for (int k = 1; k < TOPK; k++)
                            if (tk[k] > mv) { mv = tk[k]; pm = k; }
                        if (v < mv) tk[pm] = v;
                    }
                    cnt[t] = 0;
                    unsigned long long mv = tk[0];
                    #pragma unroll
                    for (int k = 1; k < TOPK; k++)
                        if (tk[k] > mv) mv = tk[k];
                    wvv[t] = fkey_unmap((uint32_t)(mv >> 32));
                }
                __syncthreads();
                #pragma unroll
                for (int mi = 0; mi < 2; mi++)
                    #pragma unroll
                    for (int qh = 0; qh < 2; qh++)
                        wvreg[mi * 2 + qh] = wvv[wm * 32 + mi * 16 + qh * 8 + rq];
            }
        }
    }

    // emit 16 candidates per (row, half); jt=31 consolidation already ran
    if (t < 64) {
        int row = rb + t;
        #pragma unroll
        for (int s = 0; s < TOPK; s++)
            g_pi[row * 32 + half * 16 + s] =
                (int)(topk[t * TOPST + s] & 0xffffffffULL);
    }
}

// ---------------- exact refine: warp-cooperative, coalesced -----------------
// Warp = row. Lane l holds fi float4-chunks l and l+32 in registers. For each
// candidate c, all lanes cooperatively load fj (coalesced) and butterfly-
// reduce the dot; lane c keeps the packed (key,idx). Then warp-min x10.
__global__ __launch_bounds__(256) void refine_kernel() {
    int t = threadIdx.x, w = t >> 5, l = t & 31;
    int i = blockIdx.x * 8 + w;
    const float4* fi4 = (const float4*)&g_f[i * DD];
    float4 a0 = fi4[l], a1 = fi4[l + 32];
    int jl = g_pi[i * 32 + l];
    float sql = g_sq[jl];
    unsigned long long pk = ~0ULL;
    #pragma unroll 4
    for (int c = 0; c < 32; c++) {
        int j = __shfl_sync(0xffffffffu, jl, c);
        float sq = __shfl_sync(0xffffffffu, sql, c);
        const float4* fj4 = (const float4*)&g_f[j * DD];
        float4 b0 = fj4[l], b1 = fj4[l + 32];
        float p = a0.x * b0.x;
        p = fmaf(a0.y, b0.y, p);
        p = fmaf(a0.z, b0.z, p);
        p = fmaf(a0.w, b0.w, p);
        p = fmaf(a1.x, b1.x, p);
        p = fmaf(a1.y, b1.y, p);
        p = fmaf(a1.z, b1.z, p);
        p = fmaf(a1.w, b1.w, p);
        #pragma unroll
        for (int o = 16; o > 0; o >>= 1)
            p += __shfl_xor_sync(0xffffffffu, p, o);
        float key = sq - 2.f * p;
        unsigned long long v =
            ((unsigned long long)fkey_map(key) << 32) | (unsigned)j;
        if (l == c) pk = v;
    }
    #pragma unroll
    for (int r = 0; r < KNN; r++) {
        unsigned long long m = pk;
        #pragma unroll
        for (int o = 16; o > 0; o >>= 1) {
            unsigned long long other = __shfl_xor_sync(0xffffffffu, m, o);
            if (other < m) m = other;
        }
        if (l == 0) g_idx[i * KNN + r] = (int)(m & 0xffffffffULL);
        if (pk == m) pk = 0xFFFFFFFFFFFFFFFFULL;
    }
}

// ---------------- Laplacian apply -------------------------------------------
__global__ __launch_bounds__(256) void zero_kernel() {
    int tid = blockIdx.x * blockDim.x + threadIdx.x;
    int stride = gridDim.x * blockDim.x;
    float4 z4 = make_float4(0.f, 0.f, 0.f, 0.f);
    for (int i = tid; i < NP * DD / 4; i += stride) ((float4*)g_z)[i] = z4;
    if (tid < NP) { g_bcnt[tid] = 0.f; g_sq[tid] = 0.f; }
}

__global__ __launch_bounds__(256) void scatter_kernel(const float* __restrict__ x) {
    __shared__ int sidx[4][KNN];
    int t = threadIdx.x;
    int i0 = blockIdx.x * 4;
    if (t < 4 * KNN) {
        int r = t / KNN, k = t % KNN;
        int e = g_idx[(i0 + r) * KNN + k];
        sidx[r][k] = e;
        atomicAdd(&g_bcnt[e], 1.0f);
    }
    __syncthreads();
    int s = t >> 6;
    int cq = (t & 63) << 2;
    const float cnorm = 0.31622776601683794f;  // 1/sqrt(10+1e-10)
    float4 xv = *(const float4*)&x[(i0 + s) * DD + cq];
    float4 y = make_float4(xv.x * cnorm, xv.y * cnorm, xv.z * cnorm, xv.w * cnorm);
    #pragma unroll
    for (int k = 0; k < KNN; k++) {
        int e = sidx[s][k];
        float* p = &g_z[e * DD + cq];
        asm volatile("red.global.add.v4.f32 [%0], {%1, %2, %3, %4};"
                     :: "l"(p), "f"(y.x), "f"(y.y), "f"(y.z), "f"(y.w) : "memory");
    }
}

__global__ __launch_bounds__(256) void gather_kernel(const float* __restrict__ x) {
    __shared__ int   sidx[4][KNN];
    __shared__ float sbis[4][KNN];
    int t = threadIdx.x;
    int i0 = blockIdx.x * 4;
    if (t < 4 * KNN) {
        int r = t / KNN, k = t % KNN;
        int e = g_idx[(i0 + r) * KNN + k];
        sidx[r][k] = e;
        sbis[r][k] = 1.0f / sqrtf(g_bcnt[e] + 1e-10f);
    }
    __syncthreads();
    int s = t >> 6;
    int cq = (t & 63) << 2;
    float4 acc = make_float4(0.f, 0.f, 0.f, 0.f);
    #pragma unroll
    for (int k = 0; k < KNN; k++) {
        int e = sidx[s][k];
        float b = sbis[s][k];
        float4 zv = *(const float4*)&g_z[e * DD + cq];
        acc.x = fmaf(b, zv.x, acc.x);
        acc.y = fmaf(b, zv.y, acc.y);
        acc.z = fmaf(b, zv.z, acc.z);
        acc.w = fmaf(b, zv.w, acc.w);
    }
    const float hc = 0.5f * 0.31622776601683794f;
    float4 xv = *(const float4*)&x[(i0 + s) * DD + cq];
    float4 h;
    h.x = xv.x - hc * acc.x;
    h.y = xv.y - hc * acc.y;
    h.z = xv.z - hc * acc.z;
    h.w = xv.w - hc * acc.w;
    *(float4*)&g_h[(i0 + s) * DD + cq] = h;
}

// ---------------- launch -----------------------------------------------------
extern "C" void kernel_launch(void* const* d_in, const int* in_sizes, int n_in,
                              void* d_out, int out_size) {
    const float* x    = (const float*)d_in[0];   // (8192, 256)
    const float* w    = (const float*)d_in[1];   // (256, 256)
    const float* wd   = (const float*)d_in[2];   // (256, 256)
    const float* bias = (const float*)d_in[3];   // (256,)
    float* out = (float*)d_out;                  // (8192, 256)

    const int KNN_SMEM = 108544;
    cudaFuncSetAttribute(knn_coarse_kernel,
                         cudaFuncAttributeMaxDynamicSharedMemorySize, KNN_SMEM);

    zero_kernel<<<1024, 256>>>();                       // g_z, g_bcnt, g_sq = 0
    gemm_f_kernel<<<dim3(DD / 64, NP / 64), 256>>>(x, wd);  // f, fb, sq (fused)
    knn_coarse_kernel<<<dim3(2, NP / 64), 256, KNN_SMEM>>>();
    refine_kernel<<<NP / 8, 256>>>();
    scatter_kernel<<<NP / 4, 256>>>(x);
    gather_kernel<<<NP / 4, 256>>>(x);
    gemm_out_kernel<<<dim3(DD / 64, NP / 64), 256>>>(w, bias, out);
}

// round 11
// speedup vs baseline: 6.9677x; 1.0711x over previous
#include <cuda_runtime.h>
#include <cuda_bf16.h>
#include <cstdint>
#include <math.h>

#define NP  8192
#define DD  256
#define KNN 10
#define CAP 65        // push-buffer entries per row (u64)
#define TOPK 16       // per-(row,half) survivors
#define TOPST 17      // topk row stride in u64 (bank-spread)

// ---------------- scratch (static device globals; no allocation) ------------
__device__ float         g_f[NP * DD];    // f fp32 row-major
__device__ __nv_bfloat16 g_fb[NP * DD];   // f bf16 row-major
__device__ float         g_sq[NP];
__device__ int           g_pi[NP * 32];   // 32 candidates per row (2 halves x 16)
__device__ int           g_idx[NP * KNN];
__device__ float         g_z[NP * DD];
__device__ float         g_bcnt[NP];
__device__ float         g_h[NP * DD];

// ---------------- ptx helpers ------------------------------------------------
__device__ __forceinline__ uint32_t smem_u32(const void* p) {
    uint32_t a;
    asm("{ .reg .u64 t; cvta.to.shared.u64 t, %1; cvt.u32.u64 %0, t; }" : "=r"(a) : "l"(p));
    return a;
}
__device__ __forceinline__ void cpasync16(uint32_t dst, const void* src) {
    asm volatile("cp.async.cg.shared.global [%0], [%1], 16;" :: "r"(dst), "l"(src));
}
#define CP_COMMIT() asm volatile("cp.async.commit_group;" ::: "memory")
#define CP_WAIT0()  asm volatile("cp.async.wait_group 0;" ::: "memory")

__device__ __forceinline__ void ldsm_x4(uint32_t* r, uint32_t addr) {
    asm volatile("ldmatrix.sync.aligned.m8n8.x4.shared.b16 {%0,%1,%2,%3}, [%4];"
                 : "=r"(r[0]), "=r"(r[1]), "=r"(r[2]), "=r"(r[3]) : "r"(addr));
}
__device__ __forceinline__ void mma_bf16(float* c, const uint32_t* a,
                                         uint32_t b0, uint32_t b1) {
    asm volatile("mma.sync.aligned.m16n8k16.row.col.f32.bf16.bf16.f32 "
                 "{%0,%1,%2,%3}, {%4,%5,%6,%7}, {%8,%9}, {%0,%1,%2,%3};"
                 : "+f"(c[0]), "+f"(c[1]), "+f"(c[2]), "+f"(c[3])
                 : "r"(a[0]), "r"(a[1]), "r"(a[2]), "r"(a[3]), "r"(b0), "r"(b1));
}
__device__ __forceinline__ uint32_t fkey_map(float k) {
    uint32_t u = __float_as_uint(k);
    return (u & 0x80000000u) ? ~u : (u | 0x80000000u);
}
__device__ __forceinline__ float fkey_unmap(uint32_t m) {
    uint32_t u = (m & 0x80000000u) ? (m & 0x7fffffffu) : ~m;
    return __uint_as_float(u);
}
// f32x2 packed fp32 (sm_100)
__device__ __forceinline__ unsigned long long pack2(float x, float y) {
    unsigned long long r;
    asm("mov.b64 %0, {%1, %2};" : "=l"(r) : "f"(x), "f"(y));
    return r;
}
__device__ __forceinline__ float2 unpack2(unsigned long long v) {
    float2 r;
    asm("mov.b64 {%0, %1}, %2;" : "=f"(r.x), "=f"(r.y) : "l"(v));
    return r;
}
#define FMA2(d, a, b) asm("fma.rn.f32x2 %0, %1, %2, %0;" : "+l"(d) : "l"(a), "l"(b))

// ---------------- GEMM 1: g_f = x @ Wd (fp32) + g_fb (bf16) + g_sq ----------
__global__ __launch_bounds__(256) void gemm_f_kernel(const float* __restrict__ A,
                                                     const float* __restrict__ B) {
    __shared__ float As[16][64];
    __shared__ float Bs[16][64];
    int t  = threadIdx.x;
    int tx = t % 16, ty = t / 16;
    int rb = blockIdx.y * 64, cb = blockIdx.x * 64;
    unsigned long long accp[4][2] = {};
    for (int k0 = 0; k0 < DD; k0 += 16) {
        {
            int row = t >> 2, kq = (t & 3) * 4;
            float4 v = *(const float4*)&A[(rb + row) * DD + k0 + kq];
            As[kq + 0][row] = v.x; As[kq + 1][row] = v.y;
            As[kq + 2][row] = v.z; As[kq + 3][row] = v.w;
        }
        {
            int krow = t >> 4, cq = (t & 15) * 4;
            *(float4*)&Bs[krow][cq] = *(const float4*)&B[(k0 + krow) * DD + cb + cq];
        }
        __syncthreads();
        #pragma unroll
        for (int kk = 0; kk < 16; kk++) {
            float4 av = *(const float4*)&As[kk][ty * 4];
            float4 bv = *(const float4*)&Bs[kk][tx * 4];
            unsigned long long bb0 = pack2(bv.x, bv.y);
            unsigned long long bb1 = pack2(bv.z, bv.w);
            float a[4] = {av.x, av.y, av.z, av.w};
            #pragma unroll
            for (int i = 0; i < 4; i++) {
                unsigned long long aa = pack2(a[i], a[i]);
                FMA2(accp[i][0], aa, bb0);
                FMA2(accp[i][1], aa, bb1);
            }
        }
        __syncthreads();
    }
    int lane = t & 31;
    #pragma unroll
    for (int i = 0; i < 4; i++) {
        int r = rb + ty * 4 + i;
        int c = cb + tx * 4;
        float2 u0 = unpack2(accp[i][0]);
        float2 u1 = unpack2(accp[i][1]);
        float4 vv = make_float4(u0.x, u0.y, u1.x, u1.y);
        *(float4*)&g_f[r * DD + c] = vv;
        __nv_bfloat162 b01 = __floats2bfloat162_rn(vv.x, vv.y);
        __nv_bfloat162 b23 = __floats2bfloat162_rn(vv.z, vv.w);
        uint2 pk;
        pk.x = *(uint32_t*)&b01;
        pk.y = *(uint32_t*)&b23;
        *(uint2*)&g_fb[r * DD + c] = pk;
        // fused sq-norm partial: reduce over the 16-thread tx group
        float sqp = vv.x * vv.x + vv.y * vv.y + vv.z * vv.z + vv.w * vv.w;
        #pragma unroll
        for (int o = 8; o > 0; o >>= 1)
            sqp += __shfl_xor_sync(0xffffffffu, sqp, o);
        if ((lane & 15) == 0) atomicAdd(&g_sq[r], sqp);
    }
}

// ---------------- GEMM 2: out = h @ W + bias --------------------------------
__global__ __launch_bounds__(256) void gemm_out_kernel(const float* __restrict__ B,
                                                       const float* __restrict__ bias,
                                                       float* __restrict__ C) {
    __shared__ float As[16][64];
    __shared__ float Bs[16][64];
    int t  = threadIdx.x;
    int tx = t % 16, ty = t / 16;
    int rb = blockIdx.y * 64, cb = blockIdx.x * 64;
    const float* A = g_h;
    unsigned long long accp[4][2] = {};
    for (int k0 = 0; k0 < DD; k0 += 16) {
        {
            int row = t >> 2, kq = (t & 3) * 4;
            float4 v = *(const float4*)&A[(rb + row) * DD + k0 + kq];
            As[kq + 0][row] = v.x; As[kq + 1][row] = v.y;
            As[kq + 2][row] = v.z; As[kq + 3][row] = v.w;
        }
        {
            int krow = t >> 4, cq = (t & 15) * 4;
            *(float4*)&Bs[krow][cq] = *(const float4*)&B[(k0 + krow) * DD + cb + cq];
        }
        __syncthreads();
        #pragma unroll
        for (int kk = 0; kk < 16; kk++) {
            float4 av = *(const float4*)&As[kk][ty * 4];
            float4 bv = *(const float4*)&Bs[kk][tx * 4];
            unsigned long long bb0 = pack2(bv.x, bv.y);
            unsigned long long bb1 = pack2(bv.z, bv.w);
            float a[4] = {av.x, av.y, av.z, av.w};
            #pragma unroll
            for (int i = 0; i < 4; i++) {
                unsigned long long aa = pack2(a[i], a[i]);
                FMA2(accp[i][0], aa, bb0);
                FMA2(accp[i][1], aa, bb1);
            }
        }
        __syncthreads();
    }
    #pragma unroll
    for (int i = 0; i < 4; i++) {
        int r = rb + ty * 4 + i;
        int c = cb + tx * 4;
        float2 u0 = unpack2(accp[i][0]);
        float2 u1 = unpack2(accp[i][1]);
        C[r * DD + c + 0] = u0.x + bias[c + 0];
        C[r * DD + c + 1] = u0.y + bias[c + 1];
        C[r * DD + c + 2] = u1.x + bias[c + 2];
        C[r * DD + c + 3] = u1.y + bias[c + 3];
    }
}

// ---------------- coarse knn: mma.sync bf16 + threshold filter --------------
// CTA: 64 rows x one 4096-col half, 2 CTAs/SM. kc fully unrolled (compile-time
// buffer parity / addressing); cp.async offsets precomputed per thread.
__global__ __launch_bounds__(256, 2) void knn_coarse_kernel() {
    extern __shared__ char dsm[];
    // layout: A 32768 | B0 16384 | B1 16384 | buf 33280 | topk 8704 |
    //         sqs 512 | cnt 256 | wvv 256   (total 108544)
    unsigned long long* buf  = (unsigned long long*)(dsm + 65536);
    unsigned long long* topk = (unsigned long long*)(dsm + 98816);
    float* sqs = (float*)(dsm + 107520);
    int*   cnt = (int*)(dsm + 108032);
    float* wvv = (float*)(dsm + 108288);

    int t = threadIdx.x, lane = t & 31, warp = t >> 5;
    int wm = warp & 1, wn = warp >> 1;
    int rb = blockIdx.y * 64;
    int half = blockIdx.x;
    int cbase = half * (NP / 2);

    uint32_t Abase  = smem_u32(dsm);
    uint32_t Bbase0 = Abase + 32768;
    uint32_t Bbase1 = Abase + 49152;

    const float INF = __int_as_float(0x7f800000);

    // init per-row structures
    if (t < 64) {
        #pragma unroll
        for (int k = 0; k < TOPK; k++) topk[t * TOPST + k] = ~0ULL;
        cnt[t] = 0;
        wvv[t] = INF;
    }

    // precomputed per-thread B-chunk load offsets (smem, gmem bytes)
    uint32_t sOffB[4]; uint32_t gOffB[4];
    #pragma unroll
    for (int i = 0; i < 4; i++) {
        int idx = t + 256 * i;
        int id = idx >> 3, g = idx & 7;
        sOffB[i] = (uint32_t)(id * 128 + ((g ^ (id & 7)) << 4));
        gOffB[i] = (uint32_t)(id * DD * 2 + g * 16);
    }
    const char* gB = (const char*)&g_fb[(size_t)cbase * DD];

    // A tile (64 rows x 256 k), granule-swizzled: g' = g ^ (row&7)
    #pragma unroll
    for (int i = 0; i < 8; i++) {
        int idx = t + 256 * i;
        int id = idx >> 5, g = idx & 31;
        cpasync16(Abase + id * 512 + ((g ^ (id & 7)) << 4),
                  &g_fb[(rb + id) * DD + g * 8]);
    }
    // B chunk 0
    #pragma unroll
    for (int i = 0; i < 4; i++)
        cpasync16(Bbase0 + sOffB[i], gB + gOffB[i]);
    CP_COMMIT();

    // per-thread ldmatrix addressing (same fragment mapping as R5/R6)
    int arow = wm * 32 + (lane & 7) + ((lane & 8) ? 8 : 0);
    uint32_t Arow0 = Abase + arow * 512;
    uint32_t Arow1 = Arow0 + 16 * 512;
    int sw  = lane & 7;
    int aka = (lane & 16) ? 1 : 0;                   // A: k +8 selector
    int bro = (lane & 7) + ((lane & 16) ? 8 : 0);    // B: n-row within pair
    int bka = (lane & 8) ? 1 : 0;                    // B: k +8 selector
    uint32_t Brow0 = (uint32_t)((wn * 32 + bro) * 128);       // pi=0 row base
    uint32_t Brow1 = (uint32_t)((wn * 32 + 16 + bro) * 128);  // pi=1 row base

    int rq = lane >> 2, cq2 = (lane & 3) * 2;
    float wvreg[4] = {INF, INF, INF, INF};           // [mi*2+qh]

    float acc[2][4][4];

    const char* pNext = gB + 128;                    // source base of chunk 1

    #pragma unroll 1
    for (int jt = 0; jt < 32; jt++) {
        #pragma unroll
        for (int kc = 0; kc < 4; kc++) {
            CP_WAIT0();
            __syncthreads();

            if (kc == 0 && t < 128) sqs[t] = g_sq[cbase + jt * 128 + t];

            // prefetch next chunk (compile-time buffer parity)
            if (jt < 31 || kc < 3) {
                uint32_t bb = ((kc + 1) & 1) ? Bbase1 : Bbase0;
                #pragma unroll
                for (int i = 0; i < 4; i++)
                    cpasync16(bb + sOffB[i], pNext + gOffB[i]);
                CP_COMMIT();
                pNext += (kc == 2) ? (128 * DD * 2 - 3 * 128) : 128;
            }

            if (kc == 0) {
                #pragma unroll
                for (int mi = 0; mi < 2; mi++)
                    #pragma unroll
                    for (int ni = 0; ni < 4; ni++)
                        #pragma unroll
                        for (int q = 0; q < 4; q++) acc[mi][ni][q] = 0.f;
            }

            uint32_t Bb = (kc & 1) ? Bbase1 : Bbase0;
            #pragma unroll
            for (int s = 0; s < 4; s++) {            // 4 k16 steps / 64-k chunk
                int ga = kc * 8 + s * 2 + aka;       // compile-time kc, s
                uint32_t a0[4], a1[4];
                ldsm_x4(a0, Arow0 + ((ga ^ sw) << 4));
                ldsm_x4(a1, Arow1 + ((ga ^ sw) << 4));
                int gb = s * 2 + bka;
                uint32_t b0[4], b1[4];
                ldsm_x4(b0, Bb + Brow0 + ((gb ^ sw) << 4));
                ldsm_x4(b1, Bb + Brow1 + ((gb ^ sw) << 4));
                mma_bf16(acc[0][0], a0, b0[0], b0[1]);
                mma_bf16(acc[0][1], a0, b0[2], b0[3]);
                mma_bf16(acc[1][0], a1, b0[0], b0[1]);
                mma_bf16(acc[1][1], a1, b0[2], b0[3]);
                mma_bf16(acc[0][2], a0, b1[0], b1[1]);
                mma_bf16(acc[0][3], a0, b1[2], b1[3]);
                mma_bf16(acc[1][2], a1, b1[0], b1[1]);
                mma_bf16(acc[1][3], a1, b1[2], b1[3]);
            }

            if (kc == 3) {
                int jb = cbase + jt * 128;
                if (jt == 0) {
                    // bootstrap: per-thread top-4 of its 8 cols per owned row
                    #pragma unroll
                    for (int mi = 0; mi < 2; mi++)
                        #pragma unroll
                        for (int qh = 0; qh < 2; qh++) {
                            int rl = wm * 32 + mi * 16 + qh * 8 + rq;
                            float bv[4] = {INF, INF, INF, INF};
                            int bc[4] = {0, 0, 0, 0};
                            #pragma unroll
                            for (int ni = 0; ni < 4; ni++)
                                #pragma unroll
                                for (int ql = 0; ql < 2; ql++) {
                                    int cl = wn * 32 + ni * 8 + cq2 + ql;
                                    float k = fmaf(-2.f, acc[mi][ni][qh * 2 + ql], sqs[cl]);
                                    if (k < bv[3]) {
                                        if (k < bv[2]) {
                                            bv[3] = bv[2]; bc[3] = bc[2];
                                            if (k < bv[1]) {
                                                bv[2] = bv[1]; bc[2] = bc[1];
                                                if (k < bv[0]) {
                                                    bv[1] = bv[0]; bc[1] = bc[0];
                                                    bv[0] = k; bc[0] = cl;
                                                } else { bv[1] = k; bc[1] = cl; }
                                            } else { bv[2] = k; bc[2] = cl; }
                                        } else { bv[3] = k; bc[3] = cl; }
                                    }
                                }
                            #pragma unroll
                            for (int s2 = 0; s2 < 4; s2++) {
                                int pos = atomicAdd(&cnt[rl], 1);
                                if (pos < CAP)
                                    buf[rl * CAP + pos] =
                                        ((unsigned long long)fkey_map(bv[s2]) << 32) |
                                        (unsigned)(jb + bc[s2]);
                            }
                        }
                } else {
                    // threshold filter: push survivors only
                    #pragma unroll
                    for (int mi = 0; mi < 2; mi++)
                        #pragma unroll
                        for (int qh = 0; qh < 2; qh++) {
                            float wv = wvreg[mi * 2 + qh];
                            int rl = wm * 32 + mi * 16 + qh * 8 + rq;
                            #pragma unroll
                            for (int ni = 0; ni < 4; ni++)
                                #pragma unroll
                                for (int ql = 0; ql < 2; ql++) {
                                    int cl = wn * 32 + ni * 8 + cq2 + ql;
                                    float k = fmaf(-2.f, acc[mi][ni][qh * 2 + ql], sqs[cl]);
                                    if (k < wv) {
                                        int pos = atomicAdd(&cnt[rl], 1);
                                        if (pos < CAP)
                                            buf[rl * CAP + pos] =
                                                ((unsigned long long)fkey_map(k) << 32) |
                                                (unsigned)(jb + cl);
                                    }
                                }
                        }
                }

                if ((jt & (jt + 1)) == 0) {   // window boundary: jt = 2^m - 1
                    __syncthreads();
                    if (t < 64) {
                        int n = cnt[t]; if (n > CAP) n = CAP;
                        unsigned long long* tk = &topk[t * TOPST];
                        for (int e = 0; e < n; e++) {
                            unsigned long long v = buf[t * CAP + e];
                            int pm = 0; unsigned long long mv = tk[0];
                            #pragma unroll
                            for (int k = 1; k < TOPK; k++)
                                if (tk[k] > mv) { mv = tk[k]; pm = k; }
                            if (v < mv) tk[pm] = v;
                        }
                        cnt[t] = 0;
                        unsigned long long mv = tk[0];
                        #pragma unroll
                        for (int k = 1; k < TOPK; k++)
                            if (tk[k] > mv) mv = tk[k];
                        wvv[t] = fkey_unmap((uint32_t)(mv >> 32));
                    }
                    __syncthreads();
                    #pragma unroll
                    for (int mi = 0; mi < 2; mi++)
                        #pragma unroll
                        for (int qh = 0; qh < 2; qh++)
                            wvreg[mi * 2 + qh] = wvv[wm * 32 + mi * 16 + qh * 8 + rq];
                }
            }
        }
    }

    // emit 16 candidates per (row, half); jt=31 consolidation already ran
    if (t < 64) {
        int row = rb + t;
        #pragma unroll
        for (int s = 0; s < TOPK; s++)
            g_pi[row * 32 + half * 16 + s] =
                (int)(topk[t * TOPST + s] & 0xffffffffULL);
    }
}

// ---------------- exact refine: warp-cooperative, coalesced -----------------
__global__ __launch_bounds__(256) void refine_kernel() {
    int t = threadIdx.x, w = t >> 5, l = t & 31;
    int i = blockIdx.x * 8 + w;
    const float4* fi4 = (const float4*)&g_f[i * DD];
    float4 a0 = fi4[l], a1 = fi4[l + 32];
    int jl = g_pi[i * 32 + l];
    float sql = g_sq[jl];
    unsigned long long pk = ~0ULL;
    #pragma unroll 4
    for (int c = 0; c < 32; c++) {
        int j = __shfl_sync(0xffffffffu, jl, c);
        float sq = __shfl_sync(0xffffffffu, sql, c);
        const float4* fj4 = (const float4*)&g_f[j * DD];
        float4 b0 = fj4[l], b1 = fj4[l + 32];
        float p = a0.x * b0.x;
        p = fmaf(a0.y, b0.y, p);
        p = fmaf(a0.z, b0.z, p);
        p = fmaf(a0.w, b0.w, p);
        p = fmaf(a1.x, b1.x, p);
        p = fmaf(a1.y, b1.y, p);
        p = fmaf(a1.z, b1.z, p);
        p = fmaf(a1.w, b1.w, p);
        #pragma unroll
        for (int o = 16; o > 0; o >>= 1)
            p += __shfl_xor_sync(0xffffffffu, p, o);
        float key = sq - 2.f * p;
        unsigned long long v =
            ((unsigned long long)fkey_map(key) << 32) | (unsigned)j;
        if (l == c) pk = v;
    }
    #pragma unroll
    for (int r = 0; r < KNN; r++) {
        unsigned long long m = pk;
        #pragma unroll
        for (int o = 16; o > 0; o >>= 1) {
            unsigned long long other = __shfl_xor_sync(0xffffffffu, m, o);
            if (other < m) m = other;
        }
        if (l == 0) g_idx[i * KNN + r] = (int)(m & 0xffffffffULL);
        if (pk == m) pk = 0xFFFFFFFFFFFFFFFFULL;
    }
}

// ---------------- Laplacian apply -------------------------------------------
__global__ __launch_bounds__(256) void zero_kernel() {
    int tid = blockIdx.x * blockDim.x + threadIdx.x;
    int stride = gridDim.x * blockDim.x;
    float4 z4 = make_float4(0.f, 0.f, 0.f, 0.f);
    for (int i = tid; i < NP * DD / 4; i += stride) ((float4*)g_z)[i] = z4;
    if (tid < NP) { g_bcnt[tid] = 0.f; g_sq[tid] = 0.f; }
}

__global__ __launch_bounds__(256) void scatter_kernel(const float* __restrict__ x) {
    __shared__ int sidx[4][KNN];
    int t = threadIdx.x;
    int i0 = blockIdx.x * 4;
    if (t < 4 * KNN) {
        int r = t / KNN, k = t % KNN;
        int e = g_idx[(i0 + r) * KNN + k];
        sidx[r][k] = e;
        atomicAdd(&g_bcnt[e], 1.0f);
    }
    __syncthreads();
    int s = t >> 6;
    int cq = (t & 63) << 2;
    const float cnorm = 0.31622776601683794f;  // 1/sqrt(10+1e-10)
    float4 xv = *(const float4*)&x[(i0 + s) * DD + cq];
    float4 y = make_float4(xv.x * cnorm, xv.y * cnorm, xv.z * cnorm, xv.w * cnorm);
    #pragma unroll
    for (int k = 0; k < KNN; k++) {
        int e = sidx[s][k];
        float* p = &g_z[e * DD + cq];
        asm volatile("red.global.add.v4.f32 [%0], {%1, %2, %3, %4};"
                     :: "l"(p), "f"(y.x), "f"(y.y), "f"(y.z), "f"(y.w) : "memory");
    }
}

__global__ __launch_bounds__(256) void gather_kernel(const float* __restrict__ x) {
    __shared__ int   sidx[4][KNN];
    __shared__ float sbis[4][KNN];
    int t = threadIdx.x;
    int i0 = blockIdx.x * 4;
    if (t < 4 * KNN) {
        int r = t / KNN, k = t % KNN;
        int e = g_idx[(i0 + r) * KNN + k];
        sidx[r][k] = e;
        sbis[r][k] = 1.0f / sqrtf(g_bcnt[e] + 1e-10f);
    }
    __syncthreads();
    int s = t >> 6;
    int cq = (t & 63) << 2;
    float4 acc = make_float4(0.f, 0.f, 0.f, 0.f);
    #pragma unroll
    for (int k = 0; k < KNN; k++) {
        int e = sidx[s][k];
        float b = sbis[s][k];
        float4 zv = *(const float4*)&g_z[e * DD + cq];
        acc.x = fmaf(b, zv.x, acc.x);
        acc.y = fmaf(b, zv.y, acc.y);
        acc.z = fmaf(b, zv.z, acc.z);
        acc.w = fmaf(b, zv.w, acc.w);
    }
    const float hc = 0.5f * 0.31622776601683794f;
    float4 xv = *(const float4*)&x[(i0 + s) * DD + cq];
    float4 h;
    h.x = xv.x - hc * acc.x;
    h.y = xv.y - hc * acc.y;
    h.z = xv.z - hc * acc.z;
    h.w = xv.w - hc * acc.w;
    *(float4*)&g_h[(i0 + s) * DD + cq] = h;
}

// ---------------- launch -----------------------------------------------------
extern "C" void kernel_launch(void* const* d_in, const int* in_sizes, int n_in,
                              void* d_out, int out_size) {
    const float* x    = (const float*)d_in[0];   // (8192, 256)
    const float* w    = (const float*)d_in[1];   // (256, 256)
    const float* wd   = (const float*)d_in[2];   // (256, 256)
    const float* bias = (const float*)d_in[3];   // (256,)
    float* out = (float*)d_out;                  // (8192, 256)

    const int KNN_SMEM = 108544;
    cudaFuncSetAttribute(knn_coarse_kernel,
                         cudaFuncAttributeMaxDynamicSharedMemorySize, KNN_SMEM);

    zero_kernel<<<1024, 256>>>();                       // g_z, g_bcnt, g_sq = 0
    gemm_f_kernel<<<dim3(DD / 64, NP / 64), 256>>>(x, wd);  // f, fb, sq (fused)
    knn_coarse_kernel<<<dim3(2, NP / 64), 256, KNN_SMEM>>>();
    refine_kernel<<<NP / 8, 256>>>();
    scatter_kernel<<<NP / 4, 256>>>(x);
    gather_kernel<<<NP / 4, 256>>>(x);
    gemm_out_kernel<<<dim3(DD / 64, NP / 64), 256>>>(w, bias, out);
}

// round 13
// speedup vs baseline: 7.0217x; 1.0078x over previous
#include <cuda_runtime.h>
#include <cuda_bf16.h>
#include <cstdint>
#include <math.h>

#define NP  8192
#define DD  256
#define KNN 10
#define CAP 65        // push-buffer entries per row (u64)
#define TOPK 16       // per-(row,half) survivors
#define TOPST 17      // topk row stride in u64 (bank-spread)

// ---------------- scratch (static device globals; no allocation) ------------
__device__ float         g_f[NP * DD];    // f fp32 row-major
__device__ __nv_bfloat16 g_fb[NP * DD];   // f bf16 row-major
__device__ float         g_sq[NP];
__device__ int           g_pi[NP * 32];   // 32 candidates per row (2 halves x 16)
__device__ int           g_idx[NP * KNN];
__device__ float         g_z[NP * DD];
__device__ float         g_bcnt[NP];
__device__ float         g_h[NP * DD];

// ---------------- ptx helpers ------------------------------------------------
__device__ __forceinline__ uint32_t smem_u32(const void* p) {
    uint32_t a;
    asm("{ .reg .u64 t; cvta.to.shared.u64 t, %1; cvt.u32.u64 %0, t; }" : "=r"(a) : "l"(p));
    return a;
}
__device__ __forceinline__ void cpasync16(uint32_t dst, const void* src) {
    asm volatile("cp.async.cg.shared.global [%0], [%1], 16;" :: "r"(dst), "l"(src));
}
#define CP_COMMIT() asm volatile("cp.async.commit_group;" ::: "memory")
#define CP_WAIT0()  asm volatile("cp.async.wait_group 0;" ::: "memory")

__device__ __forceinline__ void ldsm_x4(uint32_t* r, uint32_t addr) {
    asm volatile("ldmatrix.sync.aligned.m8n8.x4.shared.b16 {%0,%1,%2,%3}, [%4];"
                 : "=r"(r[0]), "=r"(r[1]), "=r"(r[2]), "=r"(r[3]) : "r"(addr));
}
__device__ __forceinline__ void mma_bf16(float* c, const uint32_t* a,
                                         uint32_t b0, uint32_t b1) {
    asm volatile("mma.sync.aligned.m16n8k16.row.col.f32.bf16.bf16.f32 "
                 "{%0,%1,%2,%3}, {%4,%5,%6,%7}, {%8,%9}, {%0,%1,%2,%3};"
                 : "+f"(c[0]), "+f"(c[1]), "+f"(c[2]), "+f"(c[3])
                 : "r"(a[0]), "r"(a[1]), "r"(a[2]), "r"(a[3]), "r"(b0), "r"(b1));
}
__device__ __forceinline__ uint32_t fkey_map(float k) {
    uint32_t u = __float_as_uint(k);
    return (u & 0x80000000u) ? ~u : (u | 0x80000000u);
}
__device__ __forceinline__ float fkey_unmap(uint32_t m) {
    uint32_t u = (m & 0x80000000u) ? (m & 0x7fffffffu) : ~m;
    return __uint_as_float(u);
}
// f32x2 packed fp32 (sm_100)
__device__ __forceinline__ unsigned long long pack2(float x, float y) {
    unsigned long long r;
    asm("mov.b64 %0, {%1, %2};" : "=l"(r) : "f"(x), "f"(y));
    return r;
}
__device__ __forceinline__ float2 unpack2(unsigned long long v) {
    float2 r;
    asm("mov.b64 {%0, %1}, %2;" : "=f"(r.x), "=f"(r.y) : "l"(v));
    return r;
}
#define FMA2(d, a, b) asm("fma.rn.f32x2 %0, %1, %2, %0;" : "+l"(d) : "l"(a), "l"(b))

// ---------------- GEMM 1: g_f = x @ Wd (fp32) + g_fb (bf16) + g_sq ----------
__global__ __launch_bounds__(256) void gemm_f_kernel(const float* __restrict__ A,
                                                     const float* __restrict__ B) {
    __shared__ float As[16][64];
    __shared__ float Bs[16][64];
    int t  = threadIdx.x;
    int tx = t % 16, ty = t / 16;
    int rb = blockIdx.y * 64, cb = blockIdx.x * 64;
    unsigned long long accp[4][2] = {};
    for (int k0 = 0; k0 < DD; k0 += 16) {
        {
            int row = t >> 2, kq = (t & 3) * 4;
            float4 v = *(const float4*)&A[(rb + row) * DD + k0 + kq];
            As[kq + 0][row] = v.x; As[kq + 1][row] = v.y;
            As[kq + 2][row] = v.z; As[kq + 3][row] = v.w;
        }
        {
            int krow = t >> 4, cq = (t & 15) * 4;
            *(float4*)&Bs[krow][cq] = *(const float4*)&B[(k0 + krow) * DD + cb + cq];
        }
        __syncthreads();
        #pragma unroll
        for (int kk = 0; kk < 16; kk++) {
            float4 av = *(const float4*)&As[kk][ty * 4];
            float4 bv = *(const float4*)&Bs[kk][tx * 4];
            unsigned long long bb0 = pack2(bv.x, bv.y);
            unsigned long long bb1 = pack2(bv.z, bv.w);
            float a[4] = {av.x, av.y, av.z, av.w};
            #pragma unroll
            for (int i = 0; i < 4; i++) {
                unsigned long long aa = pack2(a[i], a[i]);
                FMA2(accp[i][0], aa, bb0);
                FMA2(accp[i][1], aa, bb1);
            }
        }
        __syncthreads();
    }
    int lane = t & 31;
    #pragma unroll
    for (int i = 0; i < 4; i++) {
        int r = rb + ty * 4 + i;
        int c = cb + tx * 4;
        float2 u0 = unpack2(accp[i][0]);
        float2 u1 = unpack2(accp[i][1]);
        float4 vv = make_float4(u0.x, u0.y, u1.x, u1.y);
        *(float4*)&g_f[r * DD + c] = vv;
        __nv_bfloat162 b01 = __floats2bfloat162_rn(vv.x, vv.y);
        __nv_bfloat162 b23 = __floats2bfloat162_rn(vv.z, vv.w);
        uint2 pk;
        pk.x = *(uint32_t*)&b01;
        pk.y = *(uint32_t*)&b23;
        *(uint2*)&g_fb[r * DD + c] = pk;
        // fused sq-norm partial: reduce over the 16-thread tx group
        float sqp = vv.x * vv.x + vv.y * vv.y + vv.z * vv.z + vv.w * vv.w;
        #pragma unroll
        for (int o = 8; o > 0; o >>= 1)
            sqp += __shfl_xor_sync(0xffffffffu, sqp, o);
        if ((lane & 15) == 0) atomicAdd(&g_sq[r], sqp);
    }
}

// ---------------- GEMM 2: out = h @ W + bias --------------------------------
__global__ __launch_bounds__(256) void gemm_out_kernel(const float* __restrict__ B,
                                                       const float* __restrict__ bias,
                                                       float* __restrict__ C) {
    __shared__ float As[16][64];
    __shared__ float Bs[16][64];
    int t  = threadIdx.x;
    int tx = t % 16, ty = t / 16;
    int rb = blockIdx.y * 64, cb = blockIdx.x * 64;
    const float* A = g_h;
    unsigned long long accp[4][2] = {};
    for (int k0 = 0; k0 < DD; k0 += 16) {
        {
            int row = t >> 2, kq = (t & 3) * 4;
            float4 v = *(const float4*)&A[(rb + row) * DD + k0 + kq];
            As[kq + 0][row] = v.x; As[kq + 1][row] = v.y;
            As[kq + 2][row] = v.z; As[kq + 3][row] = v.w;
        }
        {
            int krow = t >> 4, cq = (t & 15) * 4;
            *(float4*)&Bs[krow][cq] = *(const float4*)&B[(k0 + krow) * DD + cb + cq];
        }
        __syncthreads();
        #pragma unroll
        for (int kk = 0; kk < 16; kk++) {
            float4 av = *(const float4*)&As[kk][ty * 4];
            float4 bv = *(const float4*)&Bs[kk][tx * 4];
            unsigned long long bb0 = pack2(bv.x, bv.y);
            unsigned long long bb1 = pack2(bv.z, bv.w);
            float a[4] = {av.x, av.y, av.z, av.w};
            #pragma unroll
            for (int i = 0; i < 4; i++) {
                unsigned long long aa = pack2(a[i], a[i]);
                FMA2(accp[i][0], aa, bb0);
                FMA2(accp[i][1], aa, bb1);
            }
        }
        __syncthreads();
    }
    #pragma unroll
    for (int i = 0; i < 4; i++) {
        int r = rb + ty * 4 + i;
        int c = cb + tx * 4;
        float2 u0 = unpack2(accp[i][0]);
        float2 u1 = unpack2(accp[i][1]);
        C[r * DD + c + 0] = u0.x + bias[c + 0];
        C[r * DD + c + 1] = u0.y + bias[c + 1];
        C[r * DD + c + 2] = u1.x + bias[c + 2];
        C[r * DD + c + 3] = u1.y + bias[c + 3];
    }
}

// ---------------- coarse knn: mma.sync bf16 + threshold filter --------------
// CTA: 64 rows x one 4096-col half, 2 CTAs/SM. kc fully unrolled (compile-time
// buffer parity / addressing); cp.async offsets precomputed per thread.
// Sync order (load-bearing): CP_WAIT0 -> __syncthreads -> prefetch. The wait
// MUST precede the barrier so every thread's cp.async data is visible to all.
__global__ __launch_bounds__(256, 2) void knn_coarse_kernel() {
    extern __shared__ char dsm[];
    // layout: A 32768 | B0 16384 | B1 16384 | buf 33280 | topk 8704 |
    //         sqs 512 | cnt 256 | wvv 256   (total 108544)
    unsigned long long* buf  = (unsigned long long*)(dsm + 65536);
    unsigned long long* topk = (unsigned long long*)(dsm + 98816);
    float* sqs = (float*)(dsm + 107520);
    int*   cnt = (int*)(dsm + 108032);
    float* wvv = (float*)(dsm + 108288);

    int t = threadIdx.x, lane = t & 31, warp = t >> 5;
    int wm = warp & 1, wn = warp >> 1;
    int rb = blockIdx.y * 64;
    int half = blockIdx.x;
    int cbase = half * (NP / 2);

    uint32_t Abase  = smem_u32(dsm);
    uint32_t Bbase0 = Abase + 32768;
    uint32_t Bbase1 = Abase + 49152;

    const float INF = __int_as_float(0x7f800000);

    // init per-row structures
    if (t < 64) {
        #pragma unroll
        for (int k = 0; k < TOPK; k++) topk[t * TOPST + k] = ~0ULL;
        cnt[t] = 0;
        wvv[t] = INF;
    }

    // precomputed per-thread B-chunk load offsets (smem, gmem bytes)
    uint32_t sOffB[4]; uint32_t gOffB[4];
    #pragma unroll
    for (int i = 0; i < 4; i++) {
        int idx = t + 256 * i;
        int id = idx >> 3, g = idx & 7;
        sOffB[i] = (uint32_t)(id * 128 + ((g ^ (id & 7)) << 4));
        gOffB[i] = (uint32_t)(id * DD * 2 + g * 16);
    }
    const char* gB = (const char*)&g_fb[(size_t)cbase * DD];

    // A tile (64 rows x 256 k), granule-swizzled: g' = g ^ (row&7)
    #pragma unroll
    for (int i = 0; i < 8; i++) {
        int idx = t + 256 * i;
        int id = idx >> 5, g = idx & 31;
        cpasync16(Abase + id * 512 + ((g ^ (id & 7)) << 4),
                  &g_fb[(rb + id) * DD + g * 8]);
    }
    // B chunk 0
    #pragma unroll
    for (int i = 0; i < 4; i++)
        cpasync16(Bbase0 + sOffB[i], gB + gOffB[i]);
    CP_COMMIT();

    // per-thread ldmatrix addressing (same fragment mapping as R5/R6)
    int arow = wm * 32 + (lane & 7) + ((lane & 8) ? 8 : 0);
    uint32_t Arow0 = Abase + arow * 512;
    uint32_t Arow1 = Arow0 + 16 * 512;
    int sw  = lane & 7;
    int aka = (lane & 16) ? 1 : 0;                   // A: k +8 selector
    int bro = (lane & 7) + ((lane & 16) ? 8 : 0);    // B: n-row within pair
    int bka = (lane & 8) ? 1 : 0;                    // B: k +8 selector
    uint32_t Brow0 = (uint32_t)((wn * 32 + bro) * 128);       // pi=0 row base
    uint32_t Brow1 = (uint32_t)((wn * 32 + 16 + bro) * 128);  // pi=1 row base

    int rq = lane >> 2, cq2 = (lane & 3) * 2;
    float wvreg[4] = {INF, INF, INF, INF};           // [mi*2+qh]

    float acc[2][4][4];

    const char* pNext = gB + 128;                    // source base of chunk 1

    #pragma unroll 1
    for (int jt = 0; jt < 32; jt++) {
        #pragma unroll
        for (int kc = 0; kc < 4; kc++) {
            CP_WAIT0();
            __syncthreads();

            if (kc == 0 && t < 128) sqs[t] = g_sq[cbase + jt * 128 + t];

            // prefetch next chunk (compile-time buffer parity)
            if (jt < 31 || kc < 3) {
                uint32_t bb = ((kc + 1) & 1) ? Bbase1 : Bbase0;
                #pragma unroll
                for (int i = 0; i < 4; i++)
                    cpasync16(bb + sOffB[i], pNext + gOffB[i]);
                CP_COMMIT();
                pNext += (kc == 2) ? (128 * DD * 2 - 3 * 128) : 128;
            }

            if (kc == 0) {
                #pragma unroll
                for (int mi = 0; mi < 2; mi++)
                    #pragma unroll
                    for (int ni = 0; ni < 4; ni++)
                        #pragma unroll
                        for (int q = 0; q < 4; q++) acc[mi][ni][q] = 0.f;
            }

            uint32_t Bb = (kc & 1) ? Bbase1 : Bbase0;
            #pragma unroll
            for (int s = 0; s < 4; s++) {            // 4 k16 steps / 64-k chunk
                int ga = kc * 8 + s * 2 + aka;       // compile-time kc, s
                uint32_t a0[4], a1[4];
                ldsm_x4(a0, Arow0 + ((ga ^ sw) << 4));
                ldsm_x4(a1, Arow1 + ((ga ^ sw) << 4));
                int gb = s * 2 + bka;
                uint32_t b0[4], b1[4];
                ldsm_x4(b0, Bb + Brow0 + ((gb ^ sw) << 4));
                ldsm_x4(b1, Bb + Brow1 + ((gb ^ sw) << 4));
                mma_bf16(acc[0][0], a0, b0[0], b0[1]);
                mma_bf16(acc[0][1], a0, b0[2], b0[3]);
                mma_bf16(acc[1][0], a1, b0[0], b0[1]);
                mma_bf16(acc[1][1], a1, b0[2], b0[3]);
                mma_bf16(acc[0][2], a0, b1[0], b1[1]);
                mma_bf16(acc[0][3], a0, b1[2], b1[3]);
                mma_bf16(acc[1][2], a1, b1[0], b1[1]);
                mma_bf16(acc[1][3], a1, b1[2], b1[3]);
            }

            if (kc == 3) {
                int jb = cbase + jt * 128;
                if (jt == 0) {
                    // bootstrap: per-thread top-4 of its 8 cols per owned row
                    #pragma unroll
                    for (int mi = 0; mi < 2; mi++)
                        #pragma unroll
                        for (int qh = 0; qh < 2; qh++) {
                            int rl = wm * 32 + mi * 16 + qh * 8 + rq;
                            float bv[4] = {INF, INF, INF, INF};
                            int bc[4] = {0, 0, 0, 0};
                            #pragma unroll
                            for (int ni = 0; ni < 4; ni++)
                                #pragma unroll
                                for (int ql = 0; ql < 2; ql++) {
                                    int cl = wn * 32 + ni * 8 + cq2 + ql;
                                    float k = fmaf(-2.f, acc[mi][ni][qh * 2 + ql], sqs[cl]);
                                    if (k < bv[3]) {
                                        if (k < bv[2]) {
                                            bv[3] = bv[2]; bc[3] = bc[2];
                                            if (k < bv[1]) {
                                                bv[2] = bv[1]; bc[2] = bc[1];
                                                if (k < bv[0]) {
                                                    bv[1] = bv[0]; bc[1] = bc[0];
                                                    bv[0] = k; bc[0] = cl;
                                                } else { bv[1] = k; bc[1] = cl; }
                                            } else { bv[2] = k; bc[2] = cl; }
                                        } else { bv[3] = k; bc[3] = cl; }
                                    }
                                }
                            #pragma unroll
                            for (int s2 = 0; s2 < 4; s2++) {
                                int pos = atomicAdd(&cnt[rl], 1);
                                if (pos < CAP)
                                    buf[rl * CAP + pos] =
                                        ((unsigned long long)fkey_map(bv[s2]) << 32) |
                                        (unsigned)(jb + bc[s2]);
                            }
                        }
                } else {
                    // threshold filter: push survivors only
                    #pragma unroll
                    for (int mi = 0; mi < 2; mi++)
                        #pragma unroll
                        for (int qh = 0; qh < 2; qh++) {
                            float wv = wvreg[mi * 2 + qh];
                            int rl = wm * 32 + mi * 16 + qh * 8 + rq;
                            #pragma unroll
                            for (int ni = 0; ni < 4; ni++)
                                #pragma unroll
                                for (int ql = 0; ql < 2; ql++) {
                                    int cl = wn * 32 + ni * 8 + cq2 + ql;
                                    float k = fmaf(-2.f, acc[mi][ni][qh * 2 + ql], sqs[cl]);
                                    if (k < wv) {
                                        int pos = atomicAdd(&cnt[rl], 1);
                                        if (pos < CAP)
                                            buf[rl * CAP + pos] =
                                                ((unsigned long long)fkey_map(k) << 32) |
                                                (unsigned)(jb + cl);
                                    }
                                }
                        }
                }

                if ((jt & (jt + 1)) == 0) {   // window boundary: jt = 2^m - 1
                    __syncthreads();
                    if (t < 64) {
                        int n = cnt[t]; if (n > CAP) n = CAP;
                        unsigned long long* tk = &topk[t * TOPST];
                        for (int e = 0; e < n; e++) {
                            unsigned long long v = buf[t * CAP + e];
                            int pm = 0; unsigned long long mv = tk[0];
                            #pragma unroll
                            for (int k = 1; k < TOPK; k++)
                                if (tk[k] > mv) { mv = tk[k]; pm = k; }
                            if (v < mv) tk[pm] = v;
                        }
                        cnt[t] = 0;
                        unsigned long long mv = tk[0];
                        #pragma unroll
                        for (int k = 1; k < TOPK; k++)
                            if (tk[k] > mv) mv = tk[k];
                        wvv[t] = fkey_unmap((uint32_t)(mv >> 32));
                    }
                    __syncthreads();
                    #pragma unroll
                    for (int mi = 0; mi < 2; mi++)
                        #pragma unroll
                        for (int qh = 0; qh < 2; qh++)
                            wvreg[mi * 2 + qh] = wvv[wm * 32 + mi * 16 + qh * 8 + rq];
                }
            }
        }
    }

    // emit 16 candidates per (row, half); jt=31 consolidation already ran
    if (t < 64) {
        int row = rb + t;
        #pragma unroll
        for (int s = 0; s < TOPK; s++)
            g_pi[row * 32 + half * 16 + s] =
                (int)(topk[t * TOPST + s] & 0xffffffffULL);
    }
}

// ---------------- exact refine: warp-cooperative, coalesced -----------------
__global__ __launch_bounds__(256) void refine_kernel() {
    int t = threadIdx.x, w = t >> 5, l = t & 31;
    int i = blockIdx.x * 8 + w;
    const float4* fi4 = (const float4*)&g_f[i * DD];
    float4 a0 = fi4[l], a1 = fi4[l + 32];
    int jl = g_pi[i * 32 + l];
    float sql = g_sq[jl];
    unsigned long long pk = ~0ULL;
    #pragma unroll 8
    for (int c = 0; c < 32; c++) {
        int j = __shfl_sync(0xffffffffu, jl, c);
        float sq = __shfl_sync(0xffffffffu, sql, c);
        const float4* fj4 = (const float4*)&g_f[j * DD];
        float4 b0 = fj4[l], b1 = fj4[l + 32];
        float p = a0.x * b0.x;
        p = fmaf(a0.y, b0.y, p);
        p = fmaf(a0.z, b0.z, p);
        p = fmaf(a0.w, b0.w, p);
        p = fmaf(a1.x, b1.x, p);
        p = fmaf(a1.y, b1.y, p);
        p = fmaf(a1.z, b1.z, p);
        p = fmaf(a1.w, b1.w, p);
        #pragma unroll
        for (int o = 16; o > 0; o >>= 1)
            p += __shfl_xor_sync(0xffffffffu, p, o);
        float key = sq - 2.f * p;
        unsigned long long v =
            ((unsigned long long)fkey_map(key) << 32) | (unsigned)j;
        if (l == c) pk = v;
    }
    #pragma unroll
    for (int r = 0; r < KNN; r++) {
        unsigned long long m = pk;
        #pragma unroll
        for (int o = 16; o > 0; o >>= 1) {
            unsigned long long other = __shfl_xor_sync(0xffffffffu, m, o);
            if (other < m) m = other;
        }
        if (l == 0) g_idx[i * KNN + r] = (int)(m & 0xffffffffULL);
        if (pk == m) pk = 0xFFFFFFFFFFFFFFFFULL;
    }
}

// ---------------- Laplacian apply -------------------------------------------
__global__ __launch_bounds__(256) void zero_kernel() {
    int tid = blockIdx.x * blockDim.x + threadIdx.x;
    int stride = gridDim.x * blockDim.x;
    float4 z4 = make_float4(0.f, 0.f, 0.f, 0.f);
    for (int i = tid; i < NP * DD / 4; i += stride) ((float4*)g_z)[i] = z4;
    if (tid < NP) { g_bcnt[tid] = 0.f; g_sq[tid] = 0.f; }
}

__global__ __launch_bounds__(256) void scatter_kernel(const float* __restrict__ x) {
    __shared__ int sidx[4][KNN];
    int t = threadIdx.x;
    int i0 = blockIdx.x * 4;
    if (t < 4 * KNN) {
        int r = t / KNN, k = t % KNN;
        int e = g_idx[(i0 + r) * KNN + k];
        sidx[r][k] = e;
        atomicAdd(&g_bcnt[e], 1.0f);
    }
    __syncthreads();
    int s = t >> 6;
    int cq = (t & 63) << 2;
    const float cnorm = 0.31622776601683794f;  // 1/sqrt(10+1e-10)
    float4 xv = *(const float4*)&x[(i0 + s) * DD + cq];
    float4 y = make_float4(xv.x * cnorm, xv.y * cnorm, xv.z * cnorm, xv.w * cnorm);
    #pragma unroll
    for (int k = 0; k < KNN; k++) {
        int e = sidx[s][k];
        float* p = &g_z[e * DD + cq];
        asm volatile("red.global.add.v4.f32 [%0], {%1, %2, %3, %4};"
                     :: "l"(p), "f"(y.x), "f"(y.y), "f"(y.z), "f"(y.w) : "memory");
    }
}

__global__ __launch_bounds__(256) void gather_kernel(const float* __restrict__ x) {
    __shared__ int   sidx[4][KNN];
    __shared__ float sbis[4][KNN];
    int t = threadIdx.x;
    int i0 = blockIdx.x * 4;
    if (t < 4 * KNN) {
        int r = t / KNN, k = t % KNN;
        int e = g_idx[(i0 + r) * KNN + k];
        sidx[r][k] = e;
        sbis[r][k] = 1.0f / sqrtf(g_bcnt[e] + 1e-10f);
    }
    __syncthreads();
    int s = t >> 6;
    int cq = (t & 63) << 2;
    float4 acc = make_float4(0.f, 0.f, 0.f, 0.f);
    #pragma unroll
    for (int k = 0; k < KNN; k++) {
        int e = sidx[s][k];
        float b = sbis[s][k];
        float4 zv = *(const float4*)&g_z[e * DD + cq];
        acc.x = fmaf(b, zv.x, acc.x);
        acc.y = fmaf(b, zv.y, acc.y);
        acc.z = fmaf(b, zv.z, acc.z);
        acc.w = fmaf(b, zv.w, acc.w);
    }
    const float hc = 0.5f * 0.31622776601683794f;
    float4 xv = *(const float4*)&x[(i0 + s) * DD + cq];
    float4 h;
    h.x = xv.x - hc * acc.x;
    h.y = xv.y - hc * acc.y;
    h.z = xv.z - hc * acc.z;
    h.w = xv.w - hc * acc.w;
    *(float4*)&g_h[(i0 + s) * DD + cq] = h;
}

// ---------------- launch -----------------------------------------------------
extern "C" void kernel_launch(void* const* d_in, const int* in_sizes, int n_in,
                              void* d_out, int out_size) {
    const float* x    = (const float*)d_in[0];   // (8192, 256)
    const float* w    = (const float*)d_in[1];   // (256, 256)
    const float* wd   = (const float*)d_in[2];   // (256, 256)
    const float* bias = (const float*)d_in[3];   // (256,)
    float* out = (float*)d_out;                  // (8192, 256)

    const int KNN_SMEM = 108544;
    cudaFuncSetAttribute(knn_coarse_kernel,
                         cudaFuncAttributeMaxDynamicSharedMemorySize, KNN_SMEM);

    zero_kernel<<<1024, 256>>>();                       // g_z, g_bcnt, g_sq = 0
    gemm_f_kernel<<<dim3(DD / 64, NP / 64), 256>>>(x, wd);  // f, fb, sq (fused)
    knn_coarse_kernel<<<dim3(2, NP / 64), 256, KNN_SMEM>>>();
    refine_kernel<<<NP / 8, 256>>>();
    scatter_kernel<<<NP / 4, 256>>>(x);
    gather_kernel<<<NP / 4, 256>>>(x);
    gemm_out_kernel<<<dim3(DD / 64, NP / 64), 256>>>(w, bias, out);
}